// round 1
// baseline (speedup 1.0000x reference)
#include <cuda_runtime.h>
#include <cstdint>

// ---------------- scratch (no allocations allowed) ----------------
// qkv1: [8192, 2304]  (q | k | v), row-major
// kv2 : [8192, 1536]  (k2 | v2)
// o1,o2: [8192, 768]  attention outputs in [b, n, h*64+d] layout
__device__ float g_qkv1[8192 * 2304];
__device__ float g_kv2[8192 * 1536];
__device__ float g_o1[8192 * 768];
__device__ float g_o2[8192 * 768];

// ---------------- generic NT SGEMM: C[m,n] = sum_k A[m,k] * W[woff+n,k] (+bias[n]) ----
// A: [M, K] row-major. W: [*, K] row-major. Both K-contiguous (NT).
// Tiles: BM=BN=128, BK=8, 256 threads, each thread 8x8.
__global__ __launch_bounds__(256)
void sgemm_nt(const float* __restrict__ A, const float* __restrict__ W,
              float* __restrict__ C, const float* __restrict__ bias,
              int M, int N, int K, int woff)
{
    __shared__ __align__(16) float As[8][128];
    __shared__ __align__(16) float Ws[8][128];

    const int t  = threadIdx.x;
    const int tx = t & 15;          // 0..15 -> N sub
    const int ty = t >> 4;          // 0..15 -> M sub
    const int m0 = blockIdx.y * 128;
    const int n0 = blockIdx.x * 128;

    const int lr = t >> 1;          // 0..127 row within tile
    const int lc = (t & 1) * 4;     // 0 or 4 (k offset)

    const float* Arow = A + (size_t)(m0 + lr) * K + lc;
    const float* Wrow = W + (size_t)(woff + n0 + lr) * K + lc;

    float acc[8][8];
#pragma unroll
    for (int i = 0; i < 8; i++)
#pragma unroll
        for (int j = 0; j < 8; j++) acc[i][j] = 0.f;

    for (int k0 = 0; k0 < K; k0 += 8) {
        float4 av = *(const float4*)(Arow + k0);
        float4 wv = *(const float4*)(Wrow + k0);
        As[lc + 0][lr] = av.x; As[lc + 1][lr] = av.y;
        As[lc + 2][lr] = av.z; As[lc + 3][lr] = av.w;
        Ws[lc + 0][lr] = wv.x; Ws[lc + 1][lr] = wv.y;
        Ws[lc + 2][lr] = wv.z; Ws[lc + 3][lr] = wv.w;
        __syncthreads();

#pragma unroll
        for (int kk = 0; kk < 8; kk++) {
            float4 a0 = *(const float4*)&As[kk][ty * 8];
            float4 a1 = *(const float4*)&As[kk][ty * 8 + 4];
            float4 b0 = *(const float4*)&Ws[kk][tx * 8];
            float4 b1 = *(const float4*)&Ws[kk][tx * 8 + 4];
            float a[8] = {a0.x, a0.y, a0.z, a0.w, a1.x, a1.y, a1.z, a1.w};
            float b[8] = {b0.x, b0.y, b0.z, b0.w, b1.x, b1.y, b1.z, b1.w};
#pragma unroll
            for (int i = 0; i < 8; i++)
#pragma unroll
                for (int j = 0; j < 8; j++)
                    acc[i][j] += a[i] * b[j];
        }
        __syncthreads();
    }

#pragma unroll
    for (int i = 0; i < 8; i++) {
        const int m = m0 + ty * 8 + i;
        float o[8];
#pragma unroll
        for (int j = 0; j < 8; j++) o[j] = acc[i][j];
        if (bias) {
#pragma unroll
            for (int j = 0; j < 8; j++) o[j] += bias[n0 + tx * 8 + j];
        }
        float4 c0 = make_float4(o[0], o[1], o[2], o[3]);
        float4 c1 = make_float4(o[4], o[5], o[6], o[7]);
        float* cp = C + (size_t)m * N + n0 + tx * 8;
        *(float4*)cp = c0;
        *(float4*)(cp + 4) = c1;
    }
}

// ---------------- fused flash attention, 64x64 tiles, D=64 ----------------
// grid: (16 q-tiles, 96 b*h). 256 threads: tx=t&15 (cols), ty=t>>4 (rows), each 4x4.
// Q,K stored transposed in smem (d-major) with 4-float XOR swizzle; P transposed too.
// Pst aliases Kst (reused after S is computed).

__device__ __forceinline__ int swz(int row, int col) {
    // logical (row in [0,64), col in [0,64)) -> physical index in a 64x64 tile
    // XOR amount is a multiple of 4 -> preserves order within float4 groups
    return row * 64 + (col ^ ((row & 15) << 2));
}

__global__ __launch_bounds__(256)
void attn64(const float* __restrict__ Qb, int ldq,
            const float* __restrict__ Kb, int ldk,
            const float* __restrict__ Vb, int ldv,
            float* __restrict__ Ob, int ldo)
{
    __shared__ __align__(16) float Qst[64 * 64];  // [d][q] swizzled, pre-scaled
    __shared__ __align__(16) float Kst[64 * 64];  // [d][key] swizzled; later Pst [key][q]
    __shared__ __align__(16) float Vs [64 * 64];  // [key][d] plain
    float* Pst = Kst;

    const int t  = threadIdx.x;
    const int tx = t & 15;
    const int ty = t >> 4;
    const int bh = blockIdx.y;
    const int b  = bh / 12;
    const int h  = bh % 12;
    const int q0 = blockIdx.x * 64;
    const size_t rowbase = (size_t)b * 1024;

    const float* Q  = Qb + rowbase * ldq + h * 64;
    const float* Kp = Kb + rowbase * ldk + h * 64;
    const float* Vp = Vb + rowbase * ldv + h * 64;

    // load Q tile transposed, fold in softmax scale (1/sqrt(64) = 0.125)
    for (int idx = t; idx < 4096; idx += 256) {
        int r = idx >> 6, d = idx & 63;
        Qst[swz(d, r)] = Q[(size_t)(q0 + r) * ldq + d] * 0.125f;
    }

    float m_i[4], l_i[4], acc[4][4];
#pragma unroll
    for (int i = 0; i < 4; i++) {
        m_i[i] = -1e30f;
        l_i[i] = 0.f;
#pragma unroll
        for (int j = 0; j < 4; j++) acc[i][j] = 0.f;
    }

    for (int k0 = 0; k0 < 1024; k0 += 64) {
        __syncthreads();  // previous PV / Q-store done before overwriting tiles
        for (int idx = t; idx < 4096; idx += 256) {
            int r = idx >> 6, d = idx & 63;
            Kst[swz(d, r)] = Kp[(size_t)(k0 + r) * ldk + d];
            Vs[idx]        = Vp[(size_t)(k0 + r) * ldv + d];
        }
        __syncthreads();

        // S = Q K^T (scaled)
        float s[4][4];
#pragma unroll
        for (int i = 0; i < 4; i++)
#pragma unroll
            for (int j = 0; j < 4; j++) s[i][j] = 0.f;

#pragma unroll 8
        for (int kk = 0; kk < 64; kk++) {
            const int m4 = (kk & 15) << 2;
            float4 a  = *(const float4*)&Qst[kk * 64 + ((ty * 4) ^ m4)];
            float4 bv = *(const float4*)&Kst[kk * 64 + ((tx * 4) ^ m4)];
            float av[4] = {a.x, a.y, a.z, a.w};
            float bw[4] = {bv.x, bv.y, bv.z, bv.w};
#pragma unroll
            for (int i = 0; i < 4; i++)
#pragma unroll
                for (int j = 0; j < 4; j++)
                    s[i][j] += av[i] * bw[j];
        }
        __syncthreads();  // done reading Kst; safe to overwrite as Pst

        // online softmax
        float al[4], p[4][4];
#pragma unroll
        for (int i = 0; i < 4; i++) {
            float v = fmaxf(fmaxf(s[i][0], s[i][1]), fmaxf(s[i][2], s[i][3]));
            v = fmaxf(v, __shfl_xor_sync(0xffffffffu, v, 1));
            v = fmaxf(v, __shfl_xor_sync(0xffffffffu, v, 2));
            v = fmaxf(v, __shfl_xor_sync(0xffffffffu, v, 4));
            v = fmaxf(v, __shfl_xor_sync(0xffffffffu, v, 8));
            float mnew = fmaxf(m_i[i], v);
            al[i] = __expf(m_i[i] - mnew);
            m_i[i] = mnew;
            float rs = 0.f;
#pragma unroll
            for (int j = 0; j < 4; j++) {
                p[i][j] = __expf(s[i][j] - mnew);
                rs += p[i][j];
            }
            rs += __shfl_xor_sync(0xffffffffu, rs, 1);
            rs += __shfl_xor_sync(0xffffffffu, rs, 2);
            rs += __shfl_xor_sync(0xffffffffu, rs, 4);
            rs += __shfl_xor_sync(0xffffffffu, rs, 8);
            l_i[i] = l_i[i] * al[i] + rs;
#pragma unroll
            for (int j = 0; j < 4; j++) acc[i][j] *= al[i];
        }

        // write P transposed: Pst[key][q]
#pragma unroll
        for (int j = 0; j < 4; j++) {
            int c = tx * 4 + j;
            float4 pv = make_float4(p[0][j], p[1][j], p[2][j], p[3][j]);
            *(float4*)&Pst[c * 64 + ((ty * 4) ^ ((c & 15) << 2))] = pv;
        }
        __syncthreads();

        // O += P V
#pragma unroll 8
        for (int c = 0; c < 64; c++) {
            float4 pv = *(const float4*)&Pst[c * 64 + ((ty * 4) ^ ((c & 15) << 2))];
            float4 vv = *(const float4*)&Vs[c * 64 + tx * 4];
            float pw[4] = {pv.x, pv.y, pv.z, pv.w};
            float vw[4] = {vv.x, vv.y, vv.z, vv.w};
#pragma unroll
            for (int i = 0; i < 4; i++)
#pragma unroll
                for (int j = 0; j < 4; j++)
                    acc[i][j] += pw[i] * vw[j];
        }
    }

    // epilogue: normalize + store
#pragma unroll
    for (int i = 0; i < 4; i++) {
        float inv = 1.f / l_i[i];
        size_t row = rowbase + q0 + ty * 4 + i;
        float4 o = make_float4(acc[i][0] * inv, acc[i][1] * inv,
                               acc[i][2] * inv, acc[i][3] * inv);
        *(float4*)&Ob[row * ldo + h * 64 + tx * 4] = o;
    }
}

// ---------------- launch ----------------
extern "C" void kernel_launch(void* const* d_in, const int* in_sizes, int n_in,
                              void* d_out, int out_size)
{
    const float* x      = (const float*)d_in[0];
    const float* x2     = (const float*)d_in[1];
    const float* qkv_w  = (const float*)d_in[2];  // [2304, 768]
    const float* proj_w = (const float*)d_in[3];  // [768, 768]
    const float* proj_b = (const float*)d_in[4];  // [768]
    float* out = (float*)d_out;                   // [2, 8, 1024, 768] flattened

    float *qkv1, *kv2, *o1, *o2;
    cudaGetSymbolAddress((void**)&qkv1, g_qkv1);
    cudaGetSymbolAddress((void**)&kv2,  g_kv2);
    cudaGetSymbolAddress((void**)&o1,   g_o1);
    cudaGetSymbolAddress((void**)&o2,   g_o2);

    const int M = 8192;  // B*N

    // QKV for x (full 3C) and KV for x2 (rows 768..2303 of qkv_w only)
    sgemm_nt<<<dim3(2304 / 128, M / 128), 256>>>(x,  qkv_w, qkv1, nullptr, M, 2304, 768, 0);
    sgemm_nt<<<dim3(1536 / 128, M / 128), 256>>>(x2, qkv_w, kv2,  nullptr, M, 1536, 768, 768);

    // branch 1: Q | K | V all from qkv1
    attn64<<<dim3(16, 96), 256>>>(qkv1, 2304, qkv1 + 768, 2304, qkv1 + 1536, 2304, o1, 768);
    // branch 2: shared Q from qkv1; K2 | V2 from kv2
    attn64<<<dim3(16, 96), 256>>>(qkv1, 2304, kv2, 1536, kv2 + 768, 1536, o2, 768);

    // output projections (+bias), written straight into d_out (out1 then out2)
    sgemm_nt<<<dim3(768 / 128, M / 128), 256>>>(o1, proj_w, out,             proj_b, M, 768, 768, 0);
    sgemm_nt<<<dim3(768 / 128, M / 128), 256>>>(o2, proj_w, out + M * 768,   proj_b, M, 768, 768, 0);
}

// round 3
// speedup vs baseline: 1.4739x; 1.4739x over previous
#include <cuda_runtime.h>
#include <cuda_bf16.h>
#include <cstdint>

// ================= scratch (no allocations allowed) =================
__device__ __align__(256) float g_qkv1[8192 * 2304];   // q|k|v from x
__device__ __align__(256) float g_kv2[8192 * 1536];    // k2|v2 from x2
__device__ __align__(256) float g_o1[8192 * 768];
__device__ __align__(256) float g_o2[8192 * 768];

__device__ __align__(256) __nv_bfloat16 g_xhi[8192 * 768],  g_xlo[8192 * 768];
__device__ __align__(256) __nv_bfloat16 g_x2hi[8192 * 768], g_x2lo[8192 * 768];
__device__ __align__(256) __nv_bfloat16 g_wqhi[2304 * 768], g_wqlo[2304 * 768];
__device__ __align__(256) __nv_bfloat16 g_wphi[768 * 768],  g_wplo[768 * 768];
__device__ __align__(256) __nv_bfloat16 g_o1hi[8192 * 768], g_o1lo[8192 * 768];
__device__ __align__(256) __nv_bfloat16 g_o2hi[8192 * 768], g_o2lo[8192 * 768];

// ================= helpers =================
__device__ __forceinline__ void cp16(uint32_t s, const void* g) {
    asm volatile("cp.async.cg.shared.global [%0], [%1], 16;" :: "r"(s), "l"(g));
}

__device__ __forceinline__ void ldsm4(uint32_t* r, uint32_t addr) {
    asm volatile("ldmatrix.sync.aligned.m8n8.x4.shared.b16 {%0,%1,%2,%3}, [%4];"
                 : "=r"(r[0]), "=r"(r[1]), "=r"(r[2]), "=r"(r[3]) : "r"(addr));
}

__device__ __forceinline__ void mma16816(float* c, const uint32_t* a,
                                         uint32_t b0, uint32_t b1) {
    asm volatile(
        "mma.sync.aligned.m16n8k16.row.col.f32.bf16.bf16.f32 "
        "{%0,%1,%2,%3}, {%4,%5,%6,%7}, {%8,%9}, {%0,%1,%2,%3};"
        : "+f"(c[0]), "+f"(c[1]), "+f"(c[2]), "+f"(c[3])
        : "r"(a[0]), "r"(a[1]), "r"(a[2]), "r"(a[3]), "r"(b0), "r"(b1));
}

// ================= bf16 hi/lo split =================
__global__ __launch_bounds__(256)
void split_bf16(const float4* __restrict__ src, uint2* __restrict__ hi,
                uint2* __restrict__ lo, int n4)
{
    int i = blockIdx.x * blockDim.x + threadIdx.x;
    if (i >= n4) return;
    float4 v = src[i];
    float f[4] = {v.x, v.y, v.z, v.w};
    uint32_t h[4], l[4];
#pragma unroll
    for (int j = 0; j < 4; j++) {
        __nv_bfloat16 hb = __float2bfloat16_rn(f[j]);
        float r = f[j] - __bfloat162float(hb);
        __nv_bfloat16 lb = __float2bfloat16_rn(r);
        h[j] = (uint32_t)__bfloat16_as_ushort(hb);
        l[j] = (uint32_t)__bfloat16_as_ushort(lb);
    }
    hi[i] = make_uint2(h[0] | (h[1] << 16), h[2] | (h[3] << 16));
    lo[i] = make_uint2(l[0] | (l[1] << 16), l[2] | (l[3] << 16));
}

// ================= HMMA bf16x3 GEMM =================
// C[m,n] = sum_k A[m,k]*B[woff+n,k] (+bias), 3-term bf16 split, fp32 accumulate.
// Tile 128x128xK64, 8 warps (4 m x 2 n), warp tile 32x64.
// smem per stage: Ahi | Alo | Bhi | Blo, each 128 rows x 128B (SW128 xor swizzle).
#define TILE_B   16384
#define STAGE_B  65536
#define GEMM_SMEM (2 * STAGE_B)

__global__ __launch_bounds__(256, 1)
void gemm_hmma(const __nv_bfloat16* __restrict__ Ahi, const __nv_bfloat16* __restrict__ Alo,
               const __nv_bfloat16* __restrict__ Bhi, const __nv_bfloat16* __restrict__ Blo,
               float* __restrict__ C, const float* __restrict__ bias,
               int N, int woff)
{
    extern __shared__ __align__(1024) char smem[];
    const uint32_t sb = (uint32_t)__cvta_generic_to_shared(smem);
    const int t = threadIdx.x;
    const int wid = t >> 5, lane = t & 31;
    const int m0 = blockIdx.y * 128;
    const int n0 = blockIdx.x * 128;
    const int warp_m = (wid >> 1) * 32;
    const int warp_n = (wid & 1) * 64;
    const int K = 768, NC = 12;

    float acc[2][8][4];
#pragma unroll
    for (int i = 0; i < 2; i++)
#pragma unroll
        for (int j = 0; j < 8; j++)
#pragma unroll
            for (int v = 0; v < 4; v++) acc[i][j][v] = 0.f;

    // --- per-thread load indices: 4 granules per tile (tile = 1024 granules) ---
    int lrow[4], lg[4];
    uint32_t loff[4];
#pragma unroll
    for (int i = 0; i < 4; i++) {
        int gi = t + i * 256;
        lrow[i] = gi >> 3;
        lg[i]   = gi & 7;
        loff[i] = (uint32_t)(lrow[i] * 128 + ((lg[i] ^ (lrow[i] & 7)) << 4));
    }

    const __nv_bfloat16* Ah = Ahi + (size_t)m0 * K;
    const __nv_bfloat16* Al = Alo + (size_t)m0 * K;
    const __nv_bfloat16* Bh = Bhi + (size_t)(woff + n0) * K;
    const __nv_bfloat16* Bl = Blo + (size_t)(woff + n0) * K;

    auto load_chunk = [&](int c, int st) {
        const int kc = c * 64;
        const uint32_t base = sb + st * STAGE_B;
#pragma unroll
        for (int i = 0; i < 4; i++) {
            const size_t goff = (size_t)lrow[i] * K + kc + lg[i] * 8;
            cp16(base + 0 * TILE_B + loff[i], Ah + goff);
            cp16(base + 1 * TILE_B + loff[i], Al + goff);
            cp16(base + 2 * TILE_B + loff[i], Bh + goff);
            cp16(base + 3 * TILE_B + loff[i], Bl + goff);
        }
        asm volatile("cp.async.commit_group;");
    };

    // --- ldmatrix address components ---
    const int fr   = lane & 15;       // row within 16-row fragment
    const int half = lane >> 4;       // k granule half
    const int arow = warp_m + fr;     // A rows (mi*16 keeps row&7 invariant)
    const int brow = warp_n + fr;
    const int aswz = arow & 7;
    const int bswz = brow & 7;
    const uint32_t arow_off = (uint32_t)(arow * 128);
    const uint32_t brow_off = (uint32_t)(brow * 128);

    load_chunk(0, 0);

    for (int c = 0; c < NC; ++c) {
        const int st = c & 1;
        if (c + 1 < NC) {
            load_chunk(c + 1, st ^ 1);
            asm volatile("cp.async.wait_group 1;");
        } else {
            asm volatile("cp.async.wait_group 0;");
        }
        __syncthreads();

        const uint32_t base = sb + st * STAGE_B;
#pragma unroll
        for (int kk = 0; kk < 4; kk++) {
            const int kg = kk * 2 + half;
            const uint32_t aoff = arow_off + (uint32_t)(((kg ^ aswz) << 4));
            const uint32_t boff = brow_off + (uint32_t)(((kg ^ bswz) << 4));

            uint32_t ah[2][4], al[2][4], bh[4][4], bl[4][4];
#pragma unroll
            for (int mi = 0; mi < 2; mi++) {
                ldsm4(ah[mi], base + 0 * TILE_B + aoff + mi * (16 * 128));
                ldsm4(al[mi], base + 1 * TILE_B + aoff + mi * (16 * 128));
            }
#pragma unroll
            for (int nj = 0; nj < 4; nj++) {
                ldsm4(bh[nj], base + 2 * TILE_B + boff + nj * (16 * 128));
                ldsm4(bl[nj], base + 3 * TILE_B + boff + nj * (16 * 128));
            }

#pragma unroll
            for (int mi = 0; mi < 2; mi++) {
#pragma unroll
                for (int nj = 0; nj < 4; nj++) {
                    // n-frag 0 of this n16 group: b = {r0, r2}; n-frag 1: {r1, r3}
                    mma16816(acc[mi][nj * 2],     ah[mi], bh[nj][0], bh[nj][2]);
                    mma16816(acc[mi][nj * 2 + 1], ah[mi], bh[nj][1], bh[nj][3]);
                    mma16816(acc[mi][nj * 2],     ah[mi], bl[nj][0], bl[nj][2]);
                    mma16816(acc[mi][nj * 2 + 1], ah[mi], bl[nj][1], bl[nj][3]);
                    mma16816(acc[mi][nj * 2],     al[mi], bh[nj][0], bh[nj][2]);
                    mma16816(acc[mi][nj * 2 + 1], al[mi], bh[nj][1], bh[nj][3]);
                }
            }
        }
        __syncthreads();
    }

    // --- epilogue: acc frag layout: rows lane>>2 (+8), cols (lane&3)*2 (+1) ---
#pragma unroll
    for (int mi = 0; mi < 2; mi++) {
        const int r = m0 + warp_m + mi * 16 + (lane >> 2);
#pragma unroll
        for (int j = 0; j < 8; j++) {
            const int col = n0 + warp_n + j * 8 + (lane & 3) * 2;
            float2 v0 = make_float2(acc[mi][j][0], acc[mi][j][1]);
            float2 v1 = make_float2(acc[mi][j][2], acc[mi][j][3]);
            if (bias) {
                v0.x += bias[col]; v0.y += bias[col + 1];
                v1.x += bias[col]; v1.y += bias[col + 1];
            }
            *(float2*)(C + (size_t)r * N + col)       = v0;
            *(float2*)(C + (size_t)(r + 8) * N + col) = v1;
        }
    }
}

// ================= fused flash attention (fp32 SIMT, unchanged) =================
__device__ __forceinline__ int swz(int row, int col) {
    return row * 64 + (col ^ ((row & 15) << 2));
}

__global__ __launch_bounds__(256)
void attn64(const float* __restrict__ Qb, int ldq,
            const float* __restrict__ Kb, int ldk,
            const float* __restrict__ Vb, int ldv,
            float* __restrict__ Ob, int ldo)
{
    __shared__ __align__(16) float Qst[64 * 64];
    __shared__ __align__(16) float Kst[64 * 64];
    __shared__ __align__(16) float Vs [64 * 64];
    float* Pst = Kst;

    const int t  = threadIdx.x;
    const int tx = t & 15;
    const int ty = t >> 4;
    const int bh = blockIdx.y;
    const int b  = bh / 12;
    const int h  = bh % 12;
    const int q0 = blockIdx.x * 64;
    const size_t rowbase = (size_t)b * 1024;

    const float* Q  = Qb + rowbase * ldq + h * 64;
    const float* Kp = Kb + rowbase * ldk + h * 64;
    const float* Vp = Vb + rowbase * ldv + h * 64;

    for (int idx = t; idx < 4096; idx += 256) {
        int r = idx >> 6, d = idx & 63;
        Qst[swz(d, r)] = Q[(size_t)(q0 + r) * ldq + d] * 0.125f;
    }

    float m_i[4], l_i[4], acc[4][4];
#pragma unroll
    for (int i = 0; i < 4; i++) {
        m_i[i] = -1e30f;
        l_i[i] = 0.f;
#pragma unroll
        for (int j = 0; j < 4; j++) acc[i][j] = 0.f;
    }

    for (int k0 = 0; k0 < 1024; k0 += 64) {
        __syncthreads();
        for (int idx = t; idx < 4096; idx += 256) {
            int r = idx >> 6, d = idx & 63;
            Kst[swz(d, r)] = Kp[(size_t)(k0 + r) * ldk + d];
            Vs[idx]        = Vp[(size_t)(k0 + r) * ldv + d];
        }
        __syncthreads();

        float s[4][4];
#pragma unroll
        for (int i = 0; i < 4; i++)
#pragma unroll
            for (int j = 0; j < 4; j++) s[i][j] = 0.f;

#pragma unroll 8
        for (int kk = 0; kk < 64; kk++) {
            const int m4 = (kk & 15) << 2;
            float4 a  = *(const float4*)&Qst[kk * 64 + ((ty * 4) ^ m4)];
            float4 bv = *(const float4*)&Kst[kk * 64 + ((tx * 4) ^ m4)];
            float av[4] = {a.x, a.y, a.z, a.w};
            float bw[4] = {bv.x, bv.y, bv.z, bv.w};
#pragma unroll
            for (int i = 0; i < 4; i++)
#pragma unroll
                for (int j = 0; j < 4; j++)
                    s[i][j] += av[i] * bw[j];
        }
        __syncthreads();

        float al[4], p[4][4];
#pragma unroll
        for (int i = 0; i < 4; i++) {
            float v = fmaxf(fmaxf(s[i][0], s[i][1]), fmaxf(s[i][2], s[i][3]));
            v = fmaxf(v, __shfl_xor_sync(0xffffffffu, v, 1));
            v = fmaxf(v, __shfl_xor_sync(0xffffffffu, v, 2));
            v = fmaxf(v, __shfl_xor_sync(0xffffffffu, v, 4));
            v = fmaxf(v, __shfl_xor_sync(0xffffffffu, v, 8));
            float mnew = fmaxf(m_i[i], v);
            al[i] = __expf(m_i[i] - mnew);
            m_i[i] = mnew;
            float rs = 0.f;
#pragma unroll
            for (int j = 0; j < 4; j++) {
                p[i][j] = __expf(s[i][j] - mnew);
                rs += p[i][j];
            }
            rs += __shfl_xor_sync(0xffffffffu, rs, 1);
            rs += __shfl_xor_sync(0xffffffffu, rs, 2);
            rs += __shfl_xor_sync(0xffffffffu, rs, 4);
            rs += __shfl_xor_sync(0xffffffffu, rs, 8);
            l_i[i] = l_i[i] * al[i] + rs;
#pragma unroll
            for (int j = 0; j < 4; j++) acc[i][j] *= al[i];
        }

#pragma unroll
        for (int j = 0; j < 4; j++) {
            int c = tx * 4 + j;
            float4 pv = make_float4(p[0][j], p[1][j], p[2][j], p[3][j]);
            *(float4*)&Pst[c * 64 + ((ty * 4) ^ ((c & 15) << 2))] = pv;
        }
        __syncthreads();

#pragma unroll 8
        for (int c = 0; c < 64; c++) {
            float4 pv = *(const float4*)&Pst[c * 64 + ((ty * 4) ^ ((c & 15) << 2))];
            float4 vv = *(const float4*)&Vs[c * 64 + tx * 4];
            float pw[4] = {pv.x, pv.y, pv.z, pv.w};
            float vw[4] = {vv.x, vv.y, vv.z, vv.w};
#pragma unroll
            for (int i = 0; i < 4; i++)
#pragma unroll
                for (int j = 0; j < 4; j++)
                    acc[i][j] += pw[i] * vw[j];
        }
    }

#pragma unroll
    for (int i = 0; i < 4; i++) {
        float inv = 1.f / l_i[i];
        size_t row = rowbase + q0 + ty * 4 + i;
        float4 o = make_float4(acc[i][0] * inv, acc[i][1] * inv,
                               acc[i][2] * inv, acc[i][3] * inv);
        *(float4*)&Ob[row * ldo + h * 64 + tx * 4] = o;
    }
}

// ================= launch =================
extern "C" void kernel_launch(void* const* d_in, const int* in_sizes, int n_in,
                              void* d_out, int out_size)
{
    const float* x      = (const float*)d_in[0];
    const float* x2     = (const float*)d_in[1];
    const float* qkv_w  = (const float*)d_in[2];  // [2304, 768]
    const float* proj_w = (const float*)d_in[3];  // [768, 768]
    const float* proj_b = (const float*)d_in[4];  // [768]
    float* out = (float*)d_out;

    float *qkv1, *kv2, *o1, *o2;
    __nv_bfloat16 *xhi, *xlo, *x2hi, *x2lo, *wqhi, *wqlo, *wphi, *wplo;
    __nv_bfloat16 *o1hi, *o1lo, *o2hi, *o2lo;
    cudaGetSymbolAddress((void**)&qkv1, g_qkv1);
    cudaGetSymbolAddress((void**)&kv2,  g_kv2);
    cudaGetSymbolAddress((void**)&o1,   g_o1);
    cudaGetSymbolAddress((void**)&o2,   g_o2);
    cudaGetSymbolAddress((void**)&xhi,  g_xhi);
    cudaGetSymbolAddress((void**)&xlo,  g_xlo);
    cudaGetSymbolAddress((void**)&x2hi, g_x2hi);
    cudaGetSymbolAddress((void**)&x2lo, g_x2lo);
    cudaGetSymbolAddress((void**)&wqhi, g_wqhi);
    cudaGetSymbolAddress((void**)&wqlo, g_wqlo);
    cudaGetSymbolAddress((void**)&wphi, g_wphi);
    cudaGetSymbolAddress((void**)&wplo, g_wplo);
    cudaGetSymbolAddress((void**)&o1hi, g_o1hi);
    cudaGetSymbolAddress((void**)&o1lo, g_o1lo);
    cudaGetSymbolAddress((void**)&o2hi, g_o2hi);
    cudaGetSymbolAddress((void**)&o2lo, g_o2lo);

    cudaFuncSetAttribute(gemm_hmma, cudaFuncAttributeMaxDynamicSharedMemorySize, GEMM_SMEM);

    const int M = 8192;

    // hi/lo splits of inputs + weights
    {
        int n4 = 8192 * 768 / 4;
        split_bf16<<<n4 / 256, 256>>>((const float4*)x,  (uint2*)xhi,  (uint2*)xlo,  n4);
        split_bf16<<<n4 / 256, 256>>>((const float4*)x2, (uint2*)x2hi, (uint2*)x2lo, n4);
    }
    {
        int n4 = 2304 * 768 / 4;
        split_bf16<<<n4 / 256, 256>>>((const float4*)qkv_w, (uint2*)wqhi, (uint2*)wqlo, n4);
    }
    {
        int n4 = 768 * 768 / 4;
        split_bf16<<<n4 / 256, 256>>>((const float4*)proj_w, (uint2*)wphi, (uint2*)wplo, n4);
    }

    // QKV (x) and KV (x2, weight rows 768..2303)
    gemm_hmma<<<dim3(2304 / 128, M / 128), 256, GEMM_SMEM>>>(
        xhi, xlo, wqhi, wqlo, qkv1, nullptr, 2304, 0);
    gemm_hmma<<<dim3(1536 / 128, M / 128), 256, GEMM_SMEM>>>(
        x2hi, x2lo, wqhi, wqlo, kv2, nullptr, 1536, 768);

    // attention (fp32, unchanged)
    attn64<<<dim3(16, 96), 256>>>(qkv1, 2304, qkv1 + 768, 2304, qkv1 + 1536, 2304, o1, 768);
    attn64<<<dim3(16, 96), 256>>>(qkv1, 2304, kv2, 1536, kv2 + 768, 1536, o2, 768);

    // split attention outputs, then output projections (+bias) into d_out
    {
        int n4 = 8192 * 768 / 4;
        split_bf16<<<n4 / 256, 256>>>((const float4*)o1, (uint2*)o1hi, (uint2*)o1lo, n4);
        split_bf16<<<n4 / 256, 256>>>((const float4*)o2, (uint2*)o2hi, (uint2*)o2lo, n4);
    }
    gemm_hmma<<<dim3(768 / 128, M / 128), 256, GEMM_SMEM>>>(
        o1hi, o1lo, wphi, wplo, out, proj_b, 768, 0);
    gemm_hmma<<<dim3(768 / 128, M / 128), 256, GEMM_SMEM>>>(
        o2hi, o2lo, wphi, wplo, out + (size_t)M * 768, proj_b, 768, 0);
}

// round 6
// speedup vs baseline: 2.4097x; 1.6349x over previous
#include <cuda_runtime.h>
#include <cuda_bf16.h>
#include <cuda_fp16.h>
#include <cstdint>

// ================= scratch (no allocations allowed) =================
__device__ __align__(256) float g_qkv1[8192 * 2304];   // q|k|v from x
__device__ __align__(256) float g_kv2[8192 * 1536];    // k2|v2 from x2
__device__ __align__(256) float g_o1[8192 * 768];
__device__ __align__(256) float g_o2[8192 * 768];

__device__ __align__(256) __nv_bfloat16 g_xhi[8192 * 768],  g_xlo[8192 * 768];
__device__ __align__(256) __nv_bfloat16 g_x2hi[8192 * 768], g_x2lo[8192 * 768];
__device__ __align__(256) __nv_bfloat16 g_wqhi[2304 * 768], g_wqlo[2304 * 768];
__device__ __align__(256) __nv_bfloat16 g_wphi[768 * 768],  g_wplo[768 * 768];
__device__ __align__(256) __nv_bfloat16 g_o1hi[8192 * 768], g_o1lo[8192 * 768];
__device__ __align__(256) __nv_bfloat16 g_o2hi[8192 * 768], g_o2lo[8192 * 768];

// ================= helpers =================
__device__ __forceinline__ void cp16(uint32_t s, const void* g) {
    asm volatile("cp.async.cg.shared.global [%0], [%1], 16;" :: "r"(s), "l"(g));
}

__device__ __forceinline__ void ldsm4(uint32_t* r, uint32_t addr) {
    asm volatile("ldmatrix.sync.aligned.m8n8.x4.shared.b16 {%0,%1,%2,%3}, [%4];"
                 : "=r"(r[0]), "=r"(r[1]), "=r"(r[2]), "=r"(r[3]) : "r"(addr));
}

__device__ __forceinline__ void ldsm4t(uint32_t* r, uint32_t addr) {
    asm volatile("ldmatrix.sync.aligned.m8n8.x4.trans.shared.b16 {%0,%1,%2,%3}, [%4];"
                 : "=r"(r[0]), "=r"(r[1]), "=r"(r[2]), "=r"(r[3]) : "r"(addr));
}

__device__ __forceinline__ void mma16816(float* c, const uint32_t* a,
                                         uint32_t b0, uint32_t b1) {
    asm volatile(
        "mma.sync.aligned.m16n8k16.row.col.f32.bf16.bf16.f32 "
        "{%0,%1,%2,%3}, {%4,%5,%6,%7}, {%8,%9}, {%0,%1,%2,%3};"
        : "+f"(c[0]), "+f"(c[1]), "+f"(c[2]), "+f"(c[3])
        : "r"(a[0]), "r"(a[1]), "r"(a[2]), "r"(a[3]), "r"(b0), "r"(b1));
}

__device__ __forceinline__ void mma_f16(float* c, const uint32_t* a,
                                        uint32_t b0, uint32_t b1) {
    asm volatile(
        "mma.sync.aligned.m16n8k16.row.col.f32.f16.f16.f32 "
        "{%0,%1,%2,%3}, {%4,%5,%6,%7}, {%8,%9}, {%0,%1,%2,%3};"
        : "+f"(c[0]), "+f"(c[1]), "+f"(c[2]), "+f"(c[3])
        : "r"(a[0]), "r"(a[1]), "r"(a[2]), "r"(a[3]), "r"(b0), "r"(b1));
}

__device__ __forceinline__ uint32_t h2u(__half2 h) { return *(uint32_t*)&h; }

// ================= bf16 hi/lo split =================
__global__ __launch_bounds__(256)
void split_bf16(const float4* __restrict__ src, uint2* __restrict__ hi,
                uint2* __restrict__ lo, int n4)
{
    int i = blockIdx.x * blockDim.x + threadIdx.x;
    if (i >= n4) return;
    float4 v = src[i];
    float f[4] = {v.x, v.y, v.z, v.w};
    uint32_t h[4], l[4];
#pragma unroll
    for (int j = 0; j < 4; j++) {
        __nv_bfloat16 hb = __float2bfloat16_rn(f[j]);
        float r = f[j] - __bfloat162float(hb);
        __nv_bfloat16 lb = __float2bfloat16_rn(r);
        h[j] = (uint32_t)__bfloat16_as_ushort(hb);
        l[j] = (uint32_t)__bfloat16_as_ushort(lb);
    }
    hi[i] = make_uint2(h[0] | (h[1] << 16), h[2] | (h[3] << 16));
    lo[i] = make_uint2(l[0] | (l[1] << 16), l[2] | (l[3] << 16));
}

// ================= HMMA bf16x3 GEMM (unchanged from R3) =================
#define TILE_B   16384
#define STAGE_B  65536
#define GEMM_SMEM (2 * STAGE_B)

__global__ __launch_bounds__(256, 1)
void gemm_hmma(const __nv_bfloat16* __restrict__ Ahi, const __nv_bfloat16* __restrict__ Alo,
               const __nv_bfloat16* __restrict__ Bhi, const __nv_bfloat16* __restrict__ Blo,
               float* __restrict__ C, const float* __restrict__ bias,
               int N, int woff)
{
    extern __shared__ __align__(1024) char smem[];
    const uint32_t sb = (uint32_t)__cvta_generic_to_shared(smem);
    const int t = threadIdx.x;
    const int wid = t >> 5, lane = t & 31;
    const int m0 = blockIdx.y * 128;
    const int n0 = blockIdx.x * 128;
    const int warp_m = (wid >> 1) * 32;
    const int warp_n = (wid & 1) * 64;
    const int K = 768, NC = 12;

    float acc[2][8][4];
#pragma unroll
    for (int i = 0; i < 2; i++)
#pragma unroll
        for (int j = 0; j < 8; j++)
#pragma unroll
            for (int v = 0; v < 4; v++) acc[i][j][v] = 0.f;

    int lrow[4], lg[4];
    uint32_t loff[4];
#pragma unroll
    for (int i = 0; i < 4; i++) {
        int gi = t + i * 256;
        lrow[i] = gi >> 3;
        lg[i]   = gi & 7;
        loff[i] = (uint32_t)(lrow[i] * 128 + ((lg[i] ^ (lrow[i] & 7)) << 4));
    }

    const __nv_bfloat16* Ah = Ahi + (size_t)m0 * K;
    const __nv_bfloat16* Al = Alo + (size_t)m0 * K;
    const __nv_bfloat16* Bh = Bhi + (size_t)(woff + n0) * K;
    const __nv_bfloat16* Bl = Blo + (size_t)(woff + n0) * K;

    auto load_chunk = [&](int c, int st) {
        const int kc = c * 64;
        const uint32_t base = sb + st * STAGE_B;
#pragma unroll
        for (int i = 0; i < 4; i++) {
            const size_t goff = (size_t)lrow[i] * K + kc + lg[i] * 8;
            cp16(base + 0 * TILE_B + loff[i], Ah + goff);
            cp16(base + 1 * TILE_B + loff[i], Al + goff);
            cp16(base + 2 * TILE_B + loff[i], Bh + goff);
            cp16(base + 3 * TILE_B + loff[i], Bl + goff);
        }
        asm volatile("cp.async.commit_group;");
    };

    const int fr   = lane & 15;
    const int half = lane >> 4;
    const int arow = warp_m + fr;
    const int brow = warp_n + fr;
    const int aswz = arow & 7;
    const int bswz = brow & 7;
    const uint32_t arow_off = (uint32_t)(arow * 128);
    const uint32_t brow_off = (uint32_t)(brow * 128);

    load_chunk(0, 0);

    for (int c = 0; c < NC; ++c) {
        const int st = c & 1;
        if (c + 1 < NC) {
            load_chunk(c + 1, st ^ 1);
            asm volatile("cp.async.wait_group 1;");
        } else {
            asm volatile("cp.async.wait_group 0;");
        }
        __syncthreads();

        const uint32_t base = sb + st * STAGE_B;
#pragma unroll
        for (int kk = 0; kk < 4; kk++) {
            const int kg = kk * 2 + half;
            const uint32_t aoff = arow_off + (uint32_t)(((kg ^ aswz) << 4));
            const uint32_t boff = brow_off + (uint32_t)(((kg ^ bswz) << 4));

            uint32_t ah[2][4], al[2][4], bh[4][4], bl[4][4];
#pragma unroll
            for (int mi = 0; mi < 2; mi++) {
                ldsm4(ah[mi], base + 0 * TILE_B + aoff + mi * (16 * 128));
                ldsm4(al[mi], base + 1 * TILE_B + aoff + mi * (16 * 128));
            }
#pragma unroll
            for (int nj = 0; nj < 4; nj++) {
                ldsm4(bh[nj], base + 2 * TILE_B + boff + nj * (16 * 128));
                ldsm4(bl[nj], base + 3 * TILE_B + boff + nj * (16 * 128));
            }

#pragma unroll
            for (int mi = 0; mi < 2; mi++) {
#pragma unroll
                for (int nj = 0; nj < 4; nj++) {
                    mma16816(acc[mi][nj * 2],     ah[mi], bh[nj][0], bh[nj][2]);
                    mma16816(acc[mi][nj * 2 + 1], ah[mi], bh[nj][1], bh[nj][3]);
                    mma16816(acc[mi][nj * 2],     ah[mi], bl[nj][0], bl[nj][2]);
                    mma16816(acc[mi][nj * 2 + 1], ah[mi], bl[nj][1], bl[nj][3]);
                    mma16816(acc[mi][nj * 2],     al[mi], bh[nj][0], bh[nj][2]);
                    mma16816(acc[mi][nj * 2 + 1], al[mi], bh[nj][1], bh[nj][3]);
                }
            }
        }
        __syncthreads();
    }

#pragma unroll
    for (int mi = 0; mi < 2; mi++) {
        const int r = m0 + warp_m + mi * 16 + (lane >> 2);
#pragma unroll
        for (int j = 0; j < 8; j++) {
            const int col = n0 + warp_n + j * 8 + (lane & 3) * 2;
            float2 v0 = make_float2(acc[mi][j][0], acc[mi][j][1]);
            float2 v1 = make_float2(acc[mi][j][2], acc[mi][j][3]);
            if (bias) {
                v0.x += bias[col]; v0.y += bias[col + 1];
                v1.x += bias[col]; v1.y += bias[col + 1];
            }
            *(float2*)(C + (size_t)r * N + col)       = v0;
            *(float2*)(C + (size_t)(r + 8) * N + col) = v1;
        }
    }
}

// ================= HMMA fp16x-split flash attention =================
// CTA: 128 q rows (8 warps x 16), KV chunks of 64, D=64. grid (8, 96).
// smem: Qh|Ql (128x64 fp16, SW128 swizzle), Kh|Kl, Vh|Vl (64x64 each).
#define ATT_QH 0
#define ATT_QL 16384
#define ATT_KH 32768
#define ATT_KL 40960
#define ATT_VH 49152
#define ATT_VL 57344
#define ATT_SMEM 65536

__global__ __launch_bounds__(256, 1)
void attn_hmma(const float* __restrict__ Qb, int ldq,
               const float* __restrict__ Kb, int ldk,
               const float* __restrict__ Vb, int ldv,
               float* __restrict__ Ob)
{
    extern __shared__ __align__(1024) char smem[];
    const uint32_t sb = (uint32_t)__cvta_generic_to_shared(smem);
    const int t = threadIdx.x;
    const int lane = t & 31, wid = t >> 5;
    const int warp_m = wid * 16;
    const int bh = blockIdx.y;
    const int b = bh / 12, h = bh % 12;
    const int q0 = blockIdx.x * 128;
    const size_t rowbase = (size_t)b * 1024;

    const float* Qp = Qb + (rowbase + q0) * ldq + h * 64;
    const float* Kp = Kb + rowbase * ldk + h * 64;
    const float* Vp = Vb + rowbase * ldv + h * 64;

    // ---- fill Q (scaled by 0.125, fp16 hi/lo) ----
    for (int task = t; task < 1024; task += 256) {
        const int r = task >> 3, g = task & 7;
        const float* src = Qp + (size_t)r * ldq + g * 8;
        float4 f0 = *(const float4*)src;
        float4 f1 = *(const float4*)(src + 4);
        float v[8] = {f0.x, f0.y, f0.z, f0.w, f1.x, f1.y, f1.z, f1.w};
        uint32_t hi[4], lo[4];
#pragma unroll
        for (int j = 0; j < 4; j++) {
            float a = v[2 * j] * 0.125f, c = v[2 * j + 1] * 0.125f;
            __half2 hh = __floats2half2_rn(a, c);
            float2 hf = __half22float2(hh);
            lo[j] = h2u(__floats2half2_rn(a - hf.x, c - hf.y));
            hi[j] = h2u(hh);
        }
        const uint32_t off = r * 128 + ((g ^ (r & 7)) << 4);
        *(uint4*)(smem + ATT_QH + off) = make_uint4(hi[0], hi[1], hi[2], hi[3]);
        *(uint4*)(smem + ATT_QL + off) = make_uint4(lo[0], lo[1], lo[2], lo[3]);
    }

    float m_i[2], l_i[2], accO[8][4];
    m_i[0] = m_i[1] = -1e30f;
    l_i[0] = l_i[1] = 0.f;
#pragma unroll
    for (int f = 0; f < 8; f++)
#pragma unroll
        for (int v = 0; v < 4; v++) accO[f][v] = 0.f;

    // ldmatrix address components
    const int f16  = lane & 15;
    const int gsel = lane >> 4;
    const int qrow = warp_m + f16;
    const uint32_t q_off = (uint32_t)(qrow * 128);
    const int qswz = qrow & 7;
    const int kswz = f16 & 7;
    const int vrow_l = (lane & 7) + 8 * ((lane >> 3) & 1);
    const int vswz = vrow_l & 7;

    for (int k0 = 0; k0 < 1024; k0 += 64) {
        __syncthreads();
        // ---- fill K, V hi/lo (64 rows each, 8 granules) ----
        for (int task = t; task < 1024; task += 256) {
            const int kv = task >> 9;          // 0 = K, 1 = V
            const int r = (task >> 3) & 63, g = task & 7;
            const float* src = (kv ? Vp + (size_t)(k0 + r) * ldv
                                   : Kp + (size_t)(k0 + r) * ldk) + g * 8;
            float4 f0 = *(const float4*)src;
            float4 f1 = *(const float4*)(src + 4);
            float v[8] = {f0.x, f0.y, f0.z, f0.w, f1.x, f1.y, f1.z, f1.w};
            uint32_t hi[4], lo[4];
#pragma unroll
            for (int j = 0; j < 4; j++) {
                __half2 hh = __floats2half2_rn(v[2 * j], v[2 * j + 1]);
                float2 hf = __half22float2(hh);
                lo[j] = h2u(__floats2half2_rn(v[2 * j] - hf.x, v[2 * j + 1] - hf.y));
                hi[j] = h2u(hh);
            }
            const uint32_t off = r * 128 + ((g ^ (r & 7)) << 4);
            const uint32_t baseH = kv ? ATT_VH : ATT_KH;
            const uint32_t baseL = kv ? ATT_VL : ATT_KL;
            *(uint4*)(smem + baseH + off) = make_uint4(hi[0], hi[1], hi[2], hi[3]);
            *(uint4*)(smem + baseL + off) = make_uint4(lo[0], lo[1], lo[2], lo[3]);
        }
        __syncthreads();

        // ---- S = Q K^T (3-term split) ----
        float sf[8][4];
#pragma unroll
        for (int f = 0; f < 8; f++)
#pragma unroll
            for (int v = 0; v < 4; v++) sf[f][v] = 0.f;

#pragma unroll
        for (int ks = 0; ks < 4; ks++) {
            const int kg = 2 * ks + gsel;
            uint32_t qh[4], ql[4];
            const uint32_t qa = sb + q_off + (uint32_t)((kg ^ qswz) << 4);
            ldsm4(qh, ATT_QH + qa);
            ldsm4(ql, ATT_QL + qa);
#pragma unroll
            for (int np = 0; np < 4; np++) {
                const int krow = np * 16 + f16;
                const uint32_t ka = sb + (uint32_t)(krow * 128) +
                                    (uint32_t)((kg ^ kswz) << 4);
                uint32_t kh[4], kl[4];
                ldsm4(kh, ATT_KH + ka);
                ldsm4(kl, ATT_KL + ka);
                mma_f16(sf[2 * np],     qh, kh[0], kh[2]);
                mma_f16(sf[2 * np + 1], qh, kh[1], kh[3]);
                mma_f16(sf[2 * np],     qh, kl[0], kl[2]);
                mma_f16(sf[2 * np + 1], qh, kl[1], kl[3]);
                mma_f16(sf[2 * np],     ql, kh[0], kh[2]);
                mma_f16(sf[2 * np + 1], ql, kh[1], kh[3]);
            }
        }

        // ---- online softmax ----
        float mx0 = -1e30f, mx1 = -1e30f;
#pragma unroll
        for (int f = 0; f < 8; f++) {
            mx0 = fmaxf(mx0, fmaxf(sf[f][0], sf[f][1]));
            mx1 = fmaxf(mx1, fmaxf(sf[f][2], sf[f][3]));
        }
        mx0 = fmaxf(mx0, __shfl_xor_sync(0xffffffffu, mx0, 1));
        mx0 = fmaxf(mx0, __shfl_xor_sync(0xffffffffu, mx0, 2));
        mx1 = fmaxf(mx1, __shfl_xor_sync(0xffffffffu, mx1, 1));
        mx1 = fmaxf(mx1, __shfl_xor_sync(0xffffffffu, mx1, 2));

        const float mn0 = fmaxf(m_i[0], mx0);
        const float mn1 = fmaxf(m_i[1], mx1);
        const float al0 = __expf(m_i[0] - mn0);
        const float al1 = __expf(m_i[1] - mn1);
        m_i[0] = mn0; m_i[1] = mn1;

        uint32_t ph0[8], ph1[8], pl0[8], pl1[8];
        float sum0 = 0.f, sum1 = 0.f;
#pragma unroll
        for (int f = 0; f < 8; f++) {
            float p0 = __expf(sf[f][0] - mn0);
            float p1 = __expf(sf[f][1] - mn0);
            float p2 = __expf(sf[f][2] - mn1);
            float p3 = __expf(sf[f][3] - mn1);
            sum0 += p0 + p1;
            sum1 += p2 + p3;
            __half2 a = __floats2half2_rn(p0, p1);
            float2 af = __half22float2(a);
            ph0[f] = h2u(a);
            pl0[f] = h2u(__floats2half2_rn(p0 - af.x, p1 - af.y));
            __half2 c = __floats2half2_rn(p2, p3);
            float2 cf = __half22float2(c);
            ph1[f] = h2u(c);
            pl1[f] = h2u(__floats2half2_rn(p2 - cf.x, p3 - cf.y));
        }
        sum0 += __shfl_xor_sync(0xffffffffu, sum0, 1);
        sum0 += __shfl_xor_sync(0xffffffffu, sum0, 2);
        sum1 += __shfl_xor_sync(0xffffffffu, sum1, 1);
        sum1 += __shfl_xor_sync(0xffffffffu, sum1, 2);
        l_i[0] = l_i[0] * al0 + sum0;
        l_i[1] = l_i[1] * al1 + sum1;

#pragma unroll
        for (int f = 0; f < 8; f++) {
            accO[f][0] *= al0; accO[f][1] *= al0;
            accO[f][2] *= al1; accO[f][3] *= al1;
        }

        // ---- O += P V (3-term split; P frags direct from registers) ----
#pragma unroll
        for (int ks = 0; ks < 4; ks++) {
            uint32_t ah[4] = {ph0[2 * ks], ph1[2 * ks], ph0[2 * ks + 1], ph1[2 * ks + 1]};
            uint32_t alr[4] = {pl0[2 * ks], pl1[2 * ks], pl0[2 * ks + 1], pl1[2 * ks + 1]};
            const int vrow = ks * 16 + vrow_l;
#pragma unroll
            for (int g2 = 0; g2 < 4; g2++) {
                const int vg = 2 * g2 + gsel;
                const uint32_t va = sb + (uint32_t)(vrow * 128) +
                                    (uint32_t)((vg ^ vswz) << 4);
                uint32_t vh[4], vl[4];
                ldsm4t(vh, ATT_VH + va);
                ldsm4t(vl, ATT_VL + va);
                mma_f16(accO[2 * g2],     ah, vh[0], vh[1]);
                mma_f16(accO[2 * g2 + 1], ah, vh[2], vh[3]);
                mma_f16(accO[2 * g2],     ah, vl[0], vl[1]);
                mma_f16(accO[2 * g2 + 1], ah, vl[2], vl[3]);
                mma_f16(accO[2 * g2],     alr, vh[0], vh[1]);
                mma_f16(accO[2 * g2 + 1], alr, vh[2], vh[3]);
            }
        }
    }

    // ---- epilogue ----
    const float inv0 = 1.f / l_i[0];
    const float inv1 = 1.f / l_i[1];
    const size_t r0 = rowbase + q0 + warp_m + (lane >> 2);
    const size_t r1 = r0 + 8;
    const int colb = h * 64 + (lane & 3) * 2;
#pragma unroll
    for (int f = 0; f < 8; f++) {
        *(float2*)(Ob + r0 * 768 + colb + 8 * f) =
            make_float2(accO[f][0] * inv0, accO[f][1] * inv0);
        *(float2*)(Ob + r1 * 768 + colb + 8 * f) =
            make_float2(accO[f][2] * inv1, accO[f][3] * inv1);
    }
}

// ================= launch =================
extern "C" void kernel_launch(void* const* d_in, const int* in_sizes, int n_in,
                              void* d_out, int out_size)
{
    const float* x      = (const float*)d_in[0];
    const float* x2     = (const float*)d_in[1];
    const float* qkv_w  = (const float*)d_in[2];
    const float* proj_w = (const float*)d_in[3];
    const float* proj_b = (const float*)d_in[4];
    float* out = (float*)d_out;

    float *qkv1, *kv2, *o1, *o2;
    __nv_bfloat16 *xhi, *xlo, *x2hi, *x2lo, *wqhi, *wqlo, *wphi, *wplo;
    __nv_bfloat16 *o1hi, *o1lo, *o2hi, *o2lo;
    cudaGetSymbolAddress((void**)&qkv1, g_qkv1);
    cudaGetSymbolAddress((void**)&kv2,  g_kv2);
    cudaGetSymbolAddress((void**)&o1,   g_o1);
    cudaGetSymbolAddress((void**)&o2,   g_o2);
    cudaGetSymbolAddress((void**)&xhi,  g_xhi);
    cudaGetSymbolAddress((void**)&xlo,  g_xlo);
    cudaGetSymbolAddress((void**)&x2hi, g_x2hi);
    cudaGetSymbolAddress((void**)&x2lo, g_x2lo);
    cudaGetSymbolAddress((void**)&wqhi, g_wqhi);
    cudaGetSymbolAddress((void**)&wqlo, g_wqlo);
    cudaGetSymbolAddress((void**)&wphi, g_wphi);
    cudaGetSymbolAddress((void**)&wplo, g_wplo);
    cudaGetSymbolAddress((void**)&o1hi, g_o1hi);
    cudaGetSymbolAddress((void**)&o1lo, g_o1lo);
    cudaGetSymbolAddress((void**)&o2hi, g_o2hi);
    cudaGetSymbolAddress((void**)&o2lo, g_o2lo);

    cudaFuncSetAttribute(gemm_hmma, cudaFuncAttributeMaxDynamicSharedMemorySize, GEMM_SMEM);
    cudaFuncSetAttribute(attn_hmma, cudaFuncAttributeMaxDynamicSharedMemorySize, ATT_SMEM);

    const int M = 8192;

    {
        int n4 = 8192 * 768 / 4;
        split_bf16<<<n4 / 256, 256>>>((const float4*)x,  (uint2*)xhi,  (uint2*)xlo,  n4);
        split_bf16<<<n4 / 256, 256>>>((const float4*)x2, (uint2*)x2hi, (uint2*)x2lo, n4);
    }
    {
        int n4 = 2304 * 768 / 4;
        split_bf16<<<n4 / 256, 256>>>((const float4*)qkv_w, (uint2*)wqhi, (uint2*)wqlo, n4);
    }
    {
        int n4 = 768 * 768 / 4;
        split_bf16<<<n4 / 256, 256>>>((const float4*)proj_w, (uint2*)wphi, (uint2*)wplo, n4);
    }

    gemm_hmma<<<dim3(2304 / 128, M / 128), 256, GEMM_SMEM>>>(
        xhi, xlo, wqhi, wqlo, qkv1, nullptr, 2304, 0);
    gemm_hmma<<<dim3(1536 / 128, M / 128), 256, GEMM_SMEM>>>(
        x2hi, x2lo, wqhi, wqlo, kv2, nullptr, 1536, 768);

    attn_hmma<<<dim3(8, 96), 256, ATT_SMEM>>>(qkv1, 2304, qkv1 + 768, 2304,
                                              qkv1 + 1536, 2304, o1);
    attn_hmma<<<dim3(8, 96), 256, ATT_SMEM>>>(qkv1, 2304, kv2, 1536,
                                              kv2 + 768, 1536, o2);

    {
        int n4 = 8192 * 768 / 4;
        split_bf16<<<n4 / 256, 256>>>((const float4*)o1, (uint2*)o1hi, (uint2*)o1lo, n4);
        split_bf16<<<n4 / 256, 256>>>((const float4*)o2, (uint2*)o2hi, (uint2*)o2lo, n4);
    }
    gemm_hmma<<<dim3(768 / 128, M / 128), 256, GEMM_SMEM>>>(
        o1hi, o1lo, wphi, wplo, out, proj_b, 768, 0);
    gemm_hmma<<<dim3(768 / 128, M / 128), 256, GEMM_SMEM>>>(
        o2hi, o2lo, wphi, wplo, out + (size_t)M * 768, proj_b, 768, 0);
}

// round 7
// speedup vs baseline: 2.4389x; 1.0121x over previous
#include <cuda_runtime.h>
#include <cuda_bf16.h>
#include <cuda_fp16.h>
#include <cstdint>

// ================= scratch (no allocations allowed) =================
__device__ __align__(256) float g_qkv1[8192 * 2304];   // q|k|v from x
__device__ __align__(256) float g_kv2[8192 * 1536];    // k2|v2 from x2

__device__ __align__(256) __nv_bfloat16 g_xhi[8192 * 768],  g_xlo[8192 * 768];
__device__ __align__(256) __nv_bfloat16 g_x2hi[8192 * 768], g_x2lo[8192 * 768];
__device__ __align__(256) __nv_bfloat16 g_wqhi[2304 * 768], g_wqlo[2304 * 768];
__device__ __align__(256) __nv_bfloat16 g_wphi[768 * 768],  g_wplo[768 * 768];
__device__ __align__(256) __nv_bfloat16 g_o1hi[8192 * 768], g_o1lo[8192 * 768];
__device__ __align__(256) __nv_bfloat16 g_o2hi[8192 * 768], g_o2lo[8192 * 768];

// ================= helpers =================
__device__ __forceinline__ void cp16(uint32_t s, const void* g) {
    asm volatile("cp.async.cg.shared.global [%0], [%1], 16;" :: "r"(s), "l"(g));
}

__device__ __forceinline__ void ldsm4(uint32_t* r, uint32_t addr) {
    asm volatile("ldmatrix.sync.aligned.m8n8.x4.shared.b16 {%0,%1,%2,%3}, [%4];"
                 : "=r"(r[0]), "=r"(r[1]), "=r"(r[2]), "=r"(r[3]) : "r"(addr));
}

__device__ __forceinline__ void ldsm4t(uint32_t* r, uint32_t addr) {
    asm volatile("ldmatrix.sync.aligned.m8n8.x4.trans.shared.b16 {%0,%1,%2,%3}, [%4];"
                 : "=r"(r[0]), "=r"(r[1]), "=r"(r[2]), "=r"(r[3]) : "r"(addr));
}

__device__ __forceinline__ void mma16816(float* c, const uint32_t* a,
                                         uint32_t b0, uint32_t b1) {
    asm volatile(
        "mma.sync.aligned.m16n8k16.row.col.f32.bf16.bf16.f32 "
        "{%0,%1,%2,%3}, {%4,%5,%6,%7}, {%8,%9}, {%0,%1,%2,%3};"
        : "+f"(c[0]), "+f"(c[1]), "+f"(c[2]), "+f"(c[3])
        : "r"(a[0]), "r"(a[1]), "r"(a[2]), "r"(a[3]), "r"(b0), "r"(b1));
}

__device__ __forceinline__ void mma_f16(float* c, const uint32_t* a,
                                        uint32_t b0, uint32_t b1) {
    asm volatile(
        "mma.sync.aligned.m16n8k16.row.col.f32.f16.f16.f32 "
        "{%0,%1,%2,%3}, {%4,%5,%6,%7}, {%8,%9}, {%0,%1,%2,%3};"
        : "+f"(c[0]), "+f"(c[1]), "+f"(c[2]), "+f"(c[3])
        : "r"(a[0]), "r"(a[1]), "r"(a[2]), "r"(a[3]), "r"(b0), "r"(b1));
}

__device__ __forceinline__ uint32_t h2u(__half2 h) { return *(uint32_t*)&h; }

// ================= bf16 hi/lo split =================
__global__ __launch_bounds__(256)
void split_bf16(const float4* __restrict__ src, uint2* __restrict__ hi,
                uint2* __restrict__ lo, int n4)
{
    int i = blockIdx.x * blockDim.x + threadIdx.x;
    if (i >= n4) return;
    float4 v = src[i];
    float f[4] = {v.x, v.y, v.z, v.w};
    uint32_t h[4], l[4];
#pragma unroll
    for (int j = 0; j < 4; j++) {
        __nv_bfloat16 hb = __float2bfloat16_rn(f[j]);
        float r = f[j] - __bfloat162float(hb);
        __nv_bfloat16 lb = __float2bfloat16_rn(r);
        h[j] = (uint32_t)__bfloat16_as_ushort(hb);
        l[j] = (uint32_t)__bfloat16_as_ushort(lb);
    }
    hi[i] = make_uint2(h[0] | (h[1] << 16), h[2] | (h[3] << 16));
    lo[i] = make_uint2(l[0] | (l[1] << 16), l[2] | (l[3] << 16));
}

// ================= HMMA bf16x3 GEMM (term-outer mma order) =================
#define TILE_B   16384
#define STAGE_B  65536
#define GEMM_SMEM (2 * STAGE_B)

__global__ __launch_bounds__(256, 1)
void gemm_hmma(const __nv_bfloat16* __restrict__ Ahi, const __nv_bfloat16* __restrict__ Alo,
               const __nv_bfloat16* __restrict__ Bhi, const __nv_bfloat16* __restrict__ Blo,
               float* __restrict__ C, const float* __restrict__ bias,
               int N, int woff)
{
    extern __shared__ __align__(1024) char smem[];
    const uint32_t sb = (uint32_t)__cvta_generic_to_shared(smem);
    const int t = threadIdx.x;
    const int wid = t >> 5, lane = t & 31;
    const int m0 = blockIdx.y * 128;
    const int n0 = blockIdx.x * 128;
    const int warp_m = (wid >> 1) * 32;
    const int warp_n = (wid & 1) * 64;
    const int K = 768, NC = 12;

    float acc[2][8][4];
#pragma unroll
    for (int i = 0; i < 2; i++)
#pragma unroll
        for (int j = 0; j < 8; j++)
#pragma unroll
            for (int v = 0; v < 4; v++) acc[i][j][v] = 0.f;

    int lrow[4], lg[4];
    uint32_t loff[4];
#pragma unroll
    for (int i = 0; i < 4; i++) {
        int gi = t + i * 256;
        lrow[i] = gi >> 3;
        lg[i]   = gi & 7;
        loff[i] = (uint32_t)(lrow[i] * 128 + ((lg[i] ^ (lrow[i] & 7)) << 4));
    }

    const __nv_bfloat16* Ah = Ahi + (size_t)m0 * K;
    const __nv_bfloat16* Al = Alo + (size_t)m0 * K;
    const __nv_bfloat16* Bh = Bhi + (size_t)(woff + n0) * K;
    const __nv_bfloat16* Bl = Blo + (size_t)(woff + n0) * K;

    auto load_chunk = [&](int c, int st) {
        const int kc = c * 64;
        const uint32_t base = sb + st * STAGE_B;
#pragma unroll
        for (int i = 0; i < 4; i++) {
            const size_t goff = (size_t)lrow[i] * K + kc + lg[i] * 8;
            cp16(base + 0 * TILE_B + loff[i], Ah + goff);
            cp16(base + 1 * TILE_B + loff[i], Al + goff);
            cp16(base + 2 * TILE_B + loff[i], Bh + goff);
            cp16(base + 3 * TILE_B + loff[i], Bl + goff);
        }
        asm volatile("cp.async.commit_group;");
    };

    const int fr   = lane & 15;
    const int half = lane >> 4;
    const int arow = warp_m + fr;
    const int brow = warp_n + fr;
    const int aswz = arow & 7;
    const int bswz = brow & 7;
    const uint32_t arow_off = (uint32_t)(arow * 128);
    const uint32_t brow_off = (uint32_t)(brow * 128);

    load_chunk(0, 0);

    for (int c = 0; c < NC; ++c) {
        const int st = c & 1;
        if (c + 1 < NC) {
            load_chunk(c + 1, st ^ 1);
            asm volatile("cp.async.wait_group 1;");
        } else {
            asm volatile("cp.async.wait_group 0;");
        }
        __syncthreads();

        const uint32_t base = sb + st * STAGE_B;
#pragma unroll
        for (int kk = 0; kk < 4; kk++) {
            const int kg = kk * 2 + half;
            const uint32_t aoff = arow_off + (uint32_t)(((kg ^ aswz) << 4));
            const uint32_t boff = brow_off + (uint32_t)(((kg ^ bswz) << 4));

            uint32_t ah[2][4], al[2][4], bh[4][4], bl[4][4];
#pragma unroll
            for (int mi = 0; mi < 2; mi++) {
                ldsm4(ah[mi], base + 0 * TILE_B + aoff + mi * (16 * 128));
                ldsm4(al[mi], base + 1 * TILE_B + aoff + mi * (16 * 128));
            }
#pragma unroll
            for (int nj = 0; nj < 4; nj++) {
                ldsm4(bh[nj], base + 2 * TILE_B + boff + nj * (16 * 128));
                ldsm4(bl[nj], base + 3 * TILE_B + boff + nj * (16 * 128));
            }

            // term-outer order: same-accumulator reuse distance = 16 MMAs
#pragma unroll
            for (int mi = 0; mi < 2; mi++)
#pragma unroll
                for (int nj = 0; nj < 4; nj++) {
                    mma16816(acc[mi][nj * 2],     ah[mi], bh[nj][0], bh[nj][2]);
                    mma16816(acc[mi][nj * 2 + 1], ah[mi], bh[nj][1], bh[nj][3]);
                }
#pragma unroll
            for (int mi = 0; mi < 2; mi++)
#pragma unroll
                for (int nj = 0; nj < 4; nj++) {
                    mma16816(acc[mi][nj * 2],     ah[mi], bl[nj][0], bl[nj][2]);
                    mma16816(acc[mi][nj * 2 + 1], ah[mi], bl[nj][1], bl[nj][3]);
                }
#pragma unroll
            for (int mi = 0; mi < 2; mi++)
#pragma unroll
                for (int nj = 0; nj < 4; nj++) {
                    mma16816(acc[mi][nj * 2],     al[mi], bh[nj][0], bh[nj][2]);
                    mma16816(acc[mi][nj * 2 + 1], al[mi], bh[nj][1], bh[nj][3]);
                }
        }
        __syncthreads();
    }

#pragma unroll
    for (int mi = 0; mi < 2; mi++) {
        const int r = m0 + warp_m + mi * 16 + (lane >> 2);
#pragma unroll
        for (int j = 0; j < 8; j++) {
            const int col = n0 + warp_n + j * 8 + (lane & 3) * 2;
            float2 v0 = make_float2(acc[mi][j][0], acc[mi][j][1]);
            float2 v1 = make_float2(acc[mi][j][2], acc[mi][j][3]);
            if (bias) {
                v0.x += bias[col]; v0.y += bias[col + 1];
                v1.x += bias[col]; v1.y += bias[col + 1];
            }
            *(float2*)(C + (size_t)r * N + col)       = v0;
            *(float2*)(C + (size_t)(r + 8) * N + col) = v1;
        }
    }
}

// ================= HMMA fp16x-split flash attention =================
// CTA: 128 q rows (8 warps x 16), KV chunks of 64, D=64. grid (8, 96).
// Epilogue writes bf16 hi/lo directly (feeds proj GEMM; no fp32 O round-trip).
#define ATT_QH 0
#define ATT_QL 16384
#define ATT_KH 32768
#define ATT_KL 40960
#define ATT_VH 49152
#define ATT_VL 57344
#define ATT_SMEM 65536

__global__ __launch_bounds__(256, 1)
void attn_hmma(const float* __restrict__ Qb, int ldq,
               const float* __restrict__ Kb, int ldk,
               const float* __restrict__ Vb, int ldv,
               __nv_bfloat16* __restrict__ Ohi, __nv_bfloat16* __restrict__ Olo)
{
    extern __shared__ __align__(1024) char smem[];
    const uint32_t sb = (uint32_t)__cvta_generic_to_shared(smem);
    const int t = threadIdx.x;
    const int lane = t & 31, wid = t >> 5;
    const int warp_m = wid * 16;
    const int bh = blockIdx.y;
    const int b = bh / 12, h = bh % 12;
    const int q0 = blockIdx.x * 128;
    const size_t rowbase = (size_t)b * 1024;

    const float* Qp = Qb + (rowbase + q0) * ldq + h * 64;
    const float* Kp = Kb + rowbase * ldk + h * 64;
    const float* Vp = Vb + rowbase * ldv + h * 64;

    // ---- fill Q (scaled by 0.125, fp16 hi/lo) ----
    for (int task = t; task < 1024; task += 256) {
        const int r = task >> 3, g = task & 7;
        const float* src = Qp + (size_t)r * ldq + g * 8;
        float4 f0 = *(const float4*)src;
        float4 f1 = *(const float4*)(src + 4);
        float v[8] = {f0.x, f0.y, f0.z, f0.w, f1.x, f1.y, f1.z, f1.w};
        uint32_t hi[4], lo[4];
#pragma unroll
        for (int j = 0; j < 4; j++) {
            float a = v[2 * j] * 0.125f, c = v[2 * j + 1] * 0.125f;
            __half2 hh = __floats2half2_rn(a, c);
            float2 hf = __half22float2(hh);
            lo[j] = h2u(__floats2half2_rn(a - hf.x, c - hf.y));
            hi[j] = h2u(hh);
        }
        const uint32_t off = r * 128 + ((g ^ (r & 7)) << 4);
        *(uint4*)(smem + ATT_QH + off) = make_uint4(hi[0], hi[1], hi[2], hi[3]);
        *(uint4*)(smem + ATT_QL + off) = make_uint4(lo[0], lo[1], lo[2], lo[3]);
    }

    float m_i[2], l_i[2], accO[8][4];
    m_i[0] = m_i[1] = -1e30f;
    l_i[0] = l_i[1] = 0.f;
#pragma unroll
    for (int f = 0; f < 8; f++)
#pragma unroll
        for (int v = 0; v < 4; v++) accO[f][v] = 0.f;

    const int f16  = lane & 15;
    const int gsel = lane >> 4;
    const int qrow = warp_m + f16;
    const uint32_t q_off = (uint32_t)(qrow * 128);
    const int qswz = qrow & 7;
    const int kswz = f16 & 7;
    const int vrow_l = (lane & 7) + 8 * ((lane >> 3) & 1);
    const int vswz = vrow_l & 7;

    for (int k0 = 0; k0 < 1024; k0 += 64) {
        __syncthreads();
        for (int task = t; task < 1024; task += 256) {
            const int kv = task >> 9;
            const int r = (task >> 3) & 63, g = task & 7;
            const float* src = (kv ? Vp + (size_t)(k0 + r) * ldv
                                   : Kp + (size_t)(k0 + r) * ldk) + g * 8;
            float4 f0 = *(const float4*)src;
            float4 f1 = *(const float4*)(src + 4);
            float v[8] = {f0.x, f0.y, f0.z, f0.w, f1.x, f1.y, f1.z, f1.w};
            uint32_t hi[4], lo[4];
#pragma unroll
            for (int j = 0; j < 4; j++) {
                __half2 hh = __floats2half2_rn(v[2 * j], v[2 * j + 1]);
                float2 hf = __half22float2(hh);
                lo[j] = h2u(__floats2half2_rn(v[2 * j] - hf.x, v[2 * j + 1] - hf.y));
                hi[j] = h2u(hh);
            }
            const uint32_t off = r * 128 + ((g ^ (r & 7)) << 4);
            const uint32_t baseH = kv ? ATT_VH : ATT_KH;
            const uint32_t baseL = kv ? ATT_VL : ATT_KL;
            *(uint4*)(smem + baseH + off) = make_uint4(hi[0], hi[1], hi[2], hi[3]);
            *(uint4*)(smem + baseL + off) = make_uint4(lo[0], lo[1], lo[2], lo[3]);
        }
        __syncthreads();

        // ---- S = Q K^T (term-outer; same-acc distance = 8) ----
        float sf[8][4];
#pragma unroll
        for (int f = 0; f < 8; f++)
#pragma unroll
            for (int v = 0; v < 4; v++) sf[f][v] = 0.f;

#pragma unroll
        for (int ks = 0; ks < 4; ks++) {
            const int kg = 2 * ks + gsel;
            uint32_t qh[4], ql[4];
            const uint32_t qa = sb + q_off + (uint32_t)((kg ^ qswz) << 4);
            ldsm4(qh, ATT_QH + qa);
            ldsm4(ql, ATT_QL + qa);

            uint32_t kh[4][4], kl[4][4];
#pragma unroll
            for (int np = 0; np < 4; np++) {
                const uint32_t ka = sb + (uint32_t)((np * 16 + f16) * 128) +
                                    (uint32_t)((kg ^ kswz) << 4);
                ldsm4(kh[np], ATT_KH + ka);
                ldsm4(kl[np], ATT_KL + ka);
            }
#pragma unroll
            for (int np = 0; np < 4; np++) {
                mma_f16(sf[2 * np],     qh, kh[np][0], kh[np][2]);
                mma_f16(sf[2 * np + 1], qh, kh[np][1], kh[np][3]);
            }
#pragma unroll
            for (int np = 0; np < 4; np++) {
                mma_f16(sf[2 * np],     qh, kl[np][0], kl[np][2]);
                mma_f16(sf[2 * np + 1], qh, kl[np][1], kl[np][3]);
            }
#pragma unroll
            for (int np = 0; np < 4; np++) {
                mma_f16(sf[2 * np],     ql, kh[np][0], kh[np][2]);
                mma_f16(sf[2 * np + 1], ql, kh[np][1], kh[np][3]);
            }
        }

        // ---- online softmax ----
        float mx0 = -1e30f, mx1 = -1e30f;
#pragma unroll
        for (int f = 0; f < 8; f++) {
            mx0 = fmaxf(mx0, fmaxf(sf[f][0], sf[f][1]));
            mx1 = fmaxf(mx1, fmaxf(sf[f][2], sf[f][3]));
        }
        mx0 = fmaxf(mx0, __shfl_xor_sync(0xffffffffu, mx0, 1));
        mx0 = fmaxf(mx0, __shfl_xor_sync(0xffffffffu, mx0, 2));
        mx1 = fmaxf(mx1, __shfl_xor_sync(0xffffffffu, mx1, 1));
        mx1 = fmaxf(mx1, __shfl_xor_sync(0xffffffffu, mx1, 2));

        const float mn0 = fmaxf(m_i[0], mx0);
        const float mn1 = fmaxf(m_i[1], mx1);
        const float al0 = __expf(m_i[0] - mn0);
        const float al1 = __expf(m_i[1] - mn1);
        m_i[0] = mn0; m_i[1] = mn1;

        uint32_t ph0[8], ph1[8], pl0[8], pl1[8];
        float sum0 = 0.f, sum1 = 0.f;
#pragma unroll
        for (int f = 0; f < 8; f++) {
            float p0 = __expf(sf[f][0] - mn0);
            float p1 = __expf(sf[f][1] - mn0);
            float p2 = __expf(sf[f][2] - mn1);
            float p3 = __expf(sf[f][3] - mn1);
            sum0 += p0 + p1;
            sum1 += p2 + p3;
            __half2 a = __floats2half2_rn(p0, p1);
            float2 af = __half22float2(a);
            ph0[f] = h2u(a);
            pl0[f] = h2u(__floats2half2_rn(p0 - af.x, p1 - af.y));
            __half2 c = __floats2half2_rn(p2, p3);
            float2 cf = __half22float2(c);
            ph1[f] = h2u(c);
            pl1[f] = h2u(__floats2half2_rn(p2 - cf.x, p3 - cf.y));
        }
        sum0 += __shfl_xor_sync(0xffffffffu, sum0, 1);
        sum0 += __shfl_xor_sync(0xffffffffu, sum0, 2);
        sum1 += __shfl_xor_sync(0xffffffffu, sum1, 1);
        sum1 += __shfl_xor_sync(0xffffffffu, sum1, 2);
        l_i[0] = l_i[0] * al0 + sum0;
        l_i[1] = l_i[1] * al1 + sum1;

#pragma unroll
        for (int f = 0; f < 8; f++) {
            accO[f][0] *= al0; accO[f][1] *= al0;
            accO[f][2] *= al1; accO[f][3] *= al1;
        }

        // ---- O += P V (term-outer; same-acc distance = 8) ----
#pragma unroll
        for (int ks = 0; ks < 4; ks++) {
            uint32_t ah[4]  = {ph0[2 * ks], ph1[2 * ks], ph0[2 * ks + 1], ph1[2 * ks + 1]};
            uint32_t alr[4] = {pl0[2 * ks], pl1[2 * ks], pl0[2 * ks + 1], pl1[2 * ks + 1]};
            const int vrow = ks * 16 + vrow_l;
            uint32_t vh[4][4], vl[4][4];
#pragma unroll
            for (int g2 = 0; g2 < 4; g2++) {
                const int vg = 2 * g2 + gsel;
                const uint32_t va = sb + (uint32_t)(vrow * 128) +
                                    (uint32_t)((vg ^ vswz) << 4);
                ldsm4t(vh[g2], ATT_VH + va);
                ldsm4t(vl[g2], ATT_VL + va);
            }
#pragma unroll
            for (int g2 = 0; g2 < 4; g2++) {
                mma_f16(accO[2 * g2],     ah, vh[g2][0], vh[g2][1]);
                mma_f16(accO[2 * g2 + 1], ah, vh[g2][2], vh[g2][3]);
            }
#pragma unroll
            for (int g2 = 0; g2 < 4; g2++) {
                mma_f16(accO[2 * g2],     ah, vl[g2][0], vl[g2][1]);
                mma_f16(accO[2 * g2 + 1], ah, vl[g2][2], vl[g2][3]);
            }
#pragma unroll
            for (int g2 = 0; g2 < 4; g2++) {
                mma_f16(accO[2 * g2],     alr, vh[g2][0], vh[g2][1]);
                mma_f16(accO[2 * g2 + 1], alr, vh[g2][2], vh[g2][3]);
            }
        }
    }

    // ---- epilogue: normalize + bf16 hi/lo split (feeds proj GEMM) ----
    const float inv0 = 1.f / l_i[0];
    const float inv1 = 1.f / l_i[1];
    const size_t r0 = rowbase + q0 + warp_m + (lane >> 2);
    const size_t r1 = r0 + 8;
    const int colb = h * 64 + (lane & 3) * 2;
#pragma unroll
    for (int f = 0; f < 8; f++) {
        float v00 = accO[f][0] * inv0, v01 = accO[f][1] * inv0;
        float v10 = accO[f][2] * inv1, v11 = accO[f][3] * inv1;
        __nv_bfloat16 h00 = __float2bfloat16_rn(v00);
        __nv_bfloat16 h01 = __float2bfloat16_rn(v01);
        __nv_bfloat16 h10 = __float2bfloat16_rn(v10);
        __nv_bfloat16 h11 = __float2bfloat16_rn(v11);
        __nv_bfloat16 l00 = __float2bfloat16_rn(v00 - __bfloat162float(h00));
        __nv_bfloat16 l01 = __float2bfloat16_rn(v01 - __bfloat162float(h01));
        __nv_bfloat16 l10 = __float2bfloat16_rn(v10 - __bfloat162float(h10));
        __nv_bfloat16 l11 = __float2bfloat16_rn(v11 - __bfloat162float(h11));
        const size_t o0 = r0 * 768 + colb + 8 * f;
        const size_t o1 = r1 * 768 + colb + 8 * f;
        *(ushort2*)(Ohi + o0) = make_ushort2(__bfloat16_as_ushort(h00), __bfloat16_as_ushort(h01));
        *(ushort2*)(Olo + o0) = make_ushort2(__bfloat16_as_ushort(l00), __bfloat16_as_ushort(l01));
        *(ushort2*)(Ohi + o1) = make_ushort2(__bfloat16_as_ushort(h10), __bfloat16_as_ushort(h11));
        *(ushort2*)(Olo + o1) = make_ushort2(__bfloat16_as_ushort(l10), __bfloat16_as_ushort(l11));
    }
}

// ================= launch =================
extern "C" void kernel_launch(void* const* d_in, const int* in_sizes, int n_in,
                              void* d_out, int out_size)
{
    const float* x      = (const float*)d_in[0];
    const float* x2     = (const float*)d_in[1];
    const float* qkv_w  = (const float*)d_in[2];
    const float* proj_w = (const float*)d_in[3];
    const float* proj_b = (const float*)d_in[4];
    float* out = (float*)d_out;

    float *qkv1, *kv2;
    __nv_bfloat16 *xhi, *xlo, *x2hi, *x2lo, *wqhi, *wqlo, *wphi, *wplo;
    __nv_bfloat16 *o1hi, *o1lo, *o2hi, *o2lo;
    cudaGetSymbolAddress((void**)&qkv1, g_qkv1);
    cudaGetSymbolAddress((void**)&kv2,  g_kv2);
    cudaGetSymbolAddress((void**)&xhi,  g_xhi);
    cudaGetSymbolAddress((void**)&xlo,  g_xlo);
    cudaGetSymbolAddress((void**)&x2hi, g_x2hi);
    cudaGetSymbolAddress((void**)&x2lo, g_x2lo);
    cudaGetSymbolAddress((void**)&wqhi, g_wqhi);
    cudaGetSymbolAddress((void**)&wqlo, g_wqlo);
    cudaGetSymbolAddress((void**)&wphi, g_wphi);
    cudaGetSymbolAddress((void**)&wplo, g_wplo);
    cudaGetSymbolAddress((void**)&o1hi, g_o1hi);
    cudaGetSymbolAddress((void**)&o1lo, g_o1lo);
    cudaGetSymbolAddress((void**)&o2hi, g_o2hi);
    cudaGetSymbolAddress((void**)&o2lo, g_o2lo);

    cudaFuncSetAttribute(gemm_hmma, cudaFuncAttributeMaxDynamicSharedMemorySize, GEMM_SMEM);
    cudaFuncSetAttribute(attn_hmma, cudaFuncAttributeMaxDynamicSharedMemorySize, ATT_SMEM);

    const int M = 8192;

    {
        int n4 = 8192 * 768 / 4;
        split_bf16<<<n4 / 256, 256>>>((const float4*)x,  (uint2*)xhi,  (uint2*)xlo,  n4);
        split_bf16<<<n4 / 256, 256>>>((const float4*)x2, (uint2*)x2hi, (uint2*)x2lo, n4);
    }
    {
        int n4 = 2304 * 768 / 4;
        split_bf16<<<n4 / 256, 256>>>((const float4*)qkv_w, (uint2*)wqhi, (uint2*)wqlo, n4);
    }
    {
        int n4 = 768 * 768 / 4;
        split_bf16<<<n4 / 256, 256>>>((const float4*)proj_w, (uint2*)wphi, (uint2*)wplo, n4);
    }

    gemm_hmma<<<dim3(2304 / 128, M / 128), 256, GEMM_SMEM>>>(
        xhi, xlo, wqhi, wqlo, qkv1, nullptr, 2304, 0);
    gemm_hmma<<<dim3(1536 / 128, M / 128), 256, GEMM_SMEM>>>(
        x2hi, x2lo, wqhi, wqlo, kv2, nullptr, 1536, 768);

    attn_hmma<<<dim3(8, 96), 256, ATT_SMEM>>>(qkv1, 2304, qkv1 + 768, 2304,
                                              qkv1 + 1536, 2304, o1hi, o1lo);
    attn_hmma<<<dim3(8, 96), 256, ATT_SMEM>>>(qkv1, 2304, kv2, 1536,
                                              kv2 + 768, 1536, o2hi, o2lo);

    gemm_hmma<<<dim3(768 / 128, M / 128), 256, GEMM_SMEM>>>(
        o1hi, o1lo, wphi, wplo, out, proj_b, 768, 0);
    gemm_hmma<<<dim3(768 / 128, M / 128), 256, GEMM_SMEM>>>(
        o2hi, o2lo, wphi, wplo, out + (size_t)M * 768, proj_b, 768, 0);
}

// round 9
// speedup vs baseline: 3.4632x; 1.4200x over previous
#include <cuda_runtime.h>
#include <cuda_bf16.h>
#include <cuda_fp16.h>
#include <cstdint>

// ================= scratch (no allocations allowed) =================
__device__ __align__(256) __half g_qkvh[8192 * 2304], g_qkvl[8192 * 2304]; // q|k|v fp16 hi/lo
__device__ __align__(256) __half g_kv2h[8192 * 1536], g_kv2l[8192 * 1536]; // k2|v2 fp16 hi/lo

__device__ __align__(256) __nv_bfloat16 g_xhi[8192 * 768],  g_xlo[8192 * 768];
__device__ __align__(256) __nv_bfloat16 g_x2hi[8192 * 768], g_x2lo[8192 * 768];
__device__ __align__(256) __nv_bfloat16 g_wqhi[2304 * 768], g_wqlo[2304 * 768];
__device__ __align__(256) __nv_bfloat16 g_wphi[768 * 768],  g_wplo[768 * 768];
__device__ __align__(256) __nv_bfloat16 g_o1hi[8192 * 768], g_o1lo[8192 * 768];
__device__ __align__(256) __nv_bfloat16 g_o2hi[8192 * 768], g_o2lo[8192 * 768];

// ================= helpers =================
__device__ __forceinline__ void cp16(uint32_t s, const void* g) {
    asm volatile("cp.async.cg.shared.global [%0], [%1], 16;" :: "r"(s), "l"(g));
}

__device__ __forceinline__ void ldsm4(uint32_t* r, uint32_t addr) {
    asm volatile("ldmatrix.sync.aligned.m8n8.x4.shared.b16 {%0,%1,%2,%3}, [%4];"
                 : "=r"(r[0]), "=r"(r[1]), "=r"(r[2]), "=r"(r[3]) : "r"(addr));
}

__device__ __forceinline__ void ldsm4t(uint32_t* r, uint32_t addr) {
    asm volatile("ldmatrix.sync.aligned.m8n8.x4.trans.shared.b16 {%0,%1,%2,%3}, [%4];"
                 : "=r"(r[0]), "=r"(r[1]), "=r"(r[2]), "=r"(r[3]) : "r"(addr));
}

__device__ __forceinline__ void mma16816(float* c, const uint32_t* a,
                                         uint32_t b0, uint32_t b1) {
    asm volatile(
        "mma.sync.aligned.m16n8k16.row.col.f32.bf16.bf16.f32 "
        "{%0,%1,%2,%3}, {%4,%5,%6,%7}, {%8,%9}, {%0,%1,%2,%3};"
        : "+f"(c[0]), "+f"(c[1]), "+f"(c[2]), "+f"(c[3])
        : "r"(a[0]), "r"(a[1]), "r"(a[2]), "r"(a[3]), "r"(b0), "r"(b1));
}

__device__ __forceinline__ void mma_f16(float* c, const uint32_t* a,
                                        uint32_t b0, uint32_t b1) {
    asm volatile(
        "mma.sync.aligned.m16n8k16.row.col.f32.f16.f16.f32 "
        "{%0,%1,%2,%3}, {%4,%5,%6,%7}, {%8,%9}, {%0,%1,%2,%3};"
        : "+f"(c[0]), "+f"(c[1]), "+f"(c[2]), "+f"(c[3])
        : "r"(a[0]), "r"(a[1]), "r"(a[2]), "r"(a[3]), "r"(b0), "r"(b1));
}

__device__ __forceinline__ uint32_t h2u(__half2 h) { return *(uint32_t*)&h; }

// ================= bf16 hi/lo split =================
__global__ __launch_bounds__(256)
void split_bf16(const float4* __restrict__ src, uint2* __restrict__ hi,
                uint2* __restrict__ lo, int n4)
{
    int i = blockIdx.x * blockDim.x + threadIdx.x;
    if (i >= n4) return;
    float4 v = src[i];
    float f[4] = {v.x, v.y, v.z, v.w};
    uint32_t h[4], l[4];
#pragma unroll
    for (int j = 0; j < 4; j++) {
        __nv_bfloat16 hb = __float2bfloat16_rn(f[j]);
        float r = f[j] - __bfloat162float(hb);
        __nv_bfloat16 lb = __float2bfloat16_rn(r);
        h[j] = (uint32_t)__bfloat16_as_ushort(hb);
        l[j] = (uint32_t)__bfloat16_as_ushort(lb);
    }
    hi[i] = make_uint2(h[0] | (h[1] << 16), h[2] | (h[3] << 16));
    lo[i] = make_uint2(l[0] | (l[1] << 16), l[2] | (l[3] << 16));
}

// ================= HMMA bf16x3 GEMM: 128x64 tile, 2 CTAs/SM =================
// C[m,n] = sum_k A[m,k]*B[woff+n,k]; out mode 0: fp32+bias, mode 1: fp16 hi/lo.
#define GT_AH 0
#define GT_AL 16384
#define GT_BH 32768
#define GT_BL 40960
#define G_STAGE 49152
#define GEMM_SMEM (2 * G_STAGE)

__global__ __launch_bounds__(256, 2)
void gemm_hmma(const __nv_bfloat16* __restrict__ Ahi, const __nv_bfloat16* __restrict__ Alo,
               const __nv_bfloat16* __restrict__ Bhi, const __nv_bfloat16* __restrict__ Blo,
               float* __restrict__ C, const float* __restrict__ bias,
               __half* __restrict__ Hh, __half* __restrict__ Hl,
               int N, int woff, int mode)
{
    extern __shared__ __align__(1024) char smem[];
    const uint32_t sb = (uint32_t)__cvta_generic_to_shared(smem);
    const int t = threadIdx.x;
    const int wid = t >> 5, lane = t & 31;
    const int m0 = blockIdx.y * 128;
    const int n0 = blockIdx.x * 64;
    const int warp_m = (wid >> 1) * 32;
    const int warp_n = (wid & 1) * 32;
    const int K = 768, NC = 12;

    float acc[2][4][4];
#pragma unroll
    for (int i = 0; i < 2; i++)
#pragma unroll
        for (int j = 0; j < 4; j++)
#pragma unroll
            for (int v = 0; v < 4; v++) acc[i][j][v] = 0.f;

    const __nv_bfloat16* Ah = Ahi + (size_t)m0 * K;
    const __nv_bfloat16* Al = Alo + (size_t)m0 * K;
    const __nv_bfloat16* Bh = Bhi + (size_t)(woff + n0) * K;
    const __nv_bfloat16* Bl = Blo + (size_t)(woff + n0) * K;

    auto load_chunk = [&](int c, int st) {
        const int kc = c * 64;
        const uint32_t base = sb + st * G_STAGE;
#pragma unroll
        for (int i = 0; i < 4; i++) {            // A: 1024 granules, 4/thread
            const int gi = t + i * 256;
            const int row = gi >> 3, g = gi & 7;
            const uint32_t loff = (uint32_t)(row * 128 + ((g ^ (row & 7)) << 4));
            const size_t goff = (size_t)row * K + kc + g * 8;
            cp16(base + GT_AH + loff, Ah + goff);
            cp16(base + GT_AL + loff, Al + goff);
        }
#pragma unroll
        for (int i = 0; i < 2; i++) {            // B: 512 granules, 2/thread
            const int gi = t + i * 256;
            const int row = gi >> 3, g = gi & 7;
            const uint32_t loff = (uint32_t)(row * 128 + ((g ^ (row & 7)) << 4));
            const size_t goff = (size_t)row * K + kc + g * 8;
            cp16(base + GT_BH + loff, Bh + goff);
            cp16(base + GT_BL + loff, Bl + goff);
        }
        asm volatile("cp.async.commit_group;");
    };

    const int fr   = lane & 15;
    const int half = lane >> 4;
    const int arow = warp_m + fr;
    const int brow = warp_n + fr;
    const int aswz = arow & 7;
    const int bswz = brow & 7;
    const uint32_t arow_off = (uint32_t)(arow * 128);
    const uint32_t brow_off = (uint32_t)(brow * 128);

    load_chunk(0, 0);

    for (int c = 0; c < NC; ++c) {
        const int st = c & 1;
        if (c + 1 < NC) {
            load_chunk(c + 1, st ^ 1);
            asm volatile("cp.async.wait_group 1;");
        } else {
            asm volatile("cp.async.wait_group 0;");
        }
        __syncthreads();

        const uint32_t base = sb + st * G_STAGE;
#pragma unroll
        for (int kk = 0; kk < 4; kk++) {
            const int kg = kk * 2 + half;
            const uint32_t aoff = arow_off + (uint32_t)((kg ^ aswz) << 4);
            const uint32_t boff = brow_off + (uint32_t)((kg ^ bswz) << 4);

            uint32_t ah[2][4], al[2][4], bh[2][4], bl[2][4];
#pragma unroll
            for (int mi = 0; mi < 2; mi++) {
                ldsm4(ah[mi], base + GT_AH + aoff + mi * (16 * 128));
                ldsm4(al[mi], base + GT_AL + aoff + mi * (16 * 128));
            }
#pragma unroll
            for (int bj = 0; bj < 2; bj++) {
                ldsm4(bh[bj], base + GT_BH + boff + bj * (16 * 128));
                ldsm4(bl[bj], base + GT_BL + boff + bj * (16 * 128));
            }
#pragma unroll
            for (int mi = 0; mi < 2; mi++)
#pragma unroll
                for (int bj = 0; bj < 2; bj++) {
                    mma16816(acc[mi][bj * 2],     ah[mi], bh[bj][0], bh[bj][2]);
                    mma16816(acc[mi][bj * 2 + 1], ah[mi], bh[bj][1], bh[bj][3]);
                }
#pragma unroll
            for (int mi = 0; mi < 2; mi++)
#pragma unroll
                for (int bj = 0; bj < 2; bj++) {
                    mma16816(acc[mi][bj * 2],     ah[mi], bl[bj][0], bl[bj][2]);
                    mma16816(acc[mi][bj * 2 + 1], ah[mi], bl[bj][1], bl[bj][3]);
                }
#pragma unroll
            for (int mi = 0; mi < 2; mi++)
#pragma unroll
                for (int bj = 0; bj < 2; bj++) {
                    mma16816(acc[mi][bj * 2],     al[mi], bh[bj][0], bh[bj][2]);
                    mma16816(acc[mi][bj * 2 + 1], al[mi], bh[bj][1], bh[bj][3]);
                }
        }
        __syncthreads();
    }

#pragma unroll
    for (int mi = 0; mi < 2; mi++) {
        const int r = m0 + warp_m + mi * 16 + (lane >> 2);
#pragma unroll
        for (int j = 0; j < 4; j++) {
            const int col = n0 + warp_n + j * 8 + (lane & 3) * 2;
            float v00 = acc[mi][j][0], v01 = acc[mi][j][1];
            float v10 = acc[mi][j][2], v11 = acc[mi][j][3];
            if (mode == 0) {
                const float b0 = bias[col], b1 = bias[col + 1];
                *(float2*)(C + (size_t)r * N + col)       = make_float2(v00 + b0, v01 + b1);
                *(float2*)(C + (size_t)(r + 8) * N + col) = make_float2(v10 + b0, v11 + b1);
            } else {
                __half h00 = __float2half_rn(v00), h01 = __float2half_rn(v01);
                __half h10 = __float2half_rn(v10), h11 = __float2half_rn(v11);
                __half l00 = __float2half_rn(v00 - __half2float(h00));
                __half l01 = __float2half_rn(v01 - __half2float(h01));
                __half l10 = __float2half_rn(v10 - __half2float(h10));
                __half l11 = __float2half_rn(v11 - __half2float(h11));
                const size_t o0 = (size_t)r * N + col;
                const size_t o1 = (size_t)(r + 8) * N + col;
                *(ushort2*)(Hh + o0) = make_ushort2(__half_as_ushort(h00), __half_as_ushort(h01));
                *(ushort2*)(Hl + o0) = make_ushort2(__half_as_ushort(l00), __half_as_ushort(l01));
                *(ushort2*)(Hh + o1) = make_ushort2(__half_as_ushort(h10), __half_as_ushort(h11));
                *(ushort2*)(Hl + o1) = make_ushort2(__half_as_ushort(l10), __half_as_ushort(l11));
            }
        }
    }
}

// ================= HMMA flash attention (fp16 hi/lo inputs, cp.async pipeline) ===
// smem: Q hi/lo 32KB @0; K/V double-buffered stages @32768 (32KB each).
#define ATT_QH 0
#define ATT_QL 16384
#define ATT_KV 32768
#define ATT_KV_STAGE 32768
#define ATT_SMEM 98304
#define ATT_KHo 0
#define ATT_KLo 8192
#define ATT_VHo 16384
#define ATT_VLo 24576

__global__ __launch_bounds__(256, 1)
void attn_hmma(const __half* __restrict__ Qh, const __half* __restrict__ Ql, int ldq,
               const __half* __restrict__ Kh, const __half* __restrict__ Kl,
               const __half* __restrict__ Vh, const __half* __restrict__ Vl, int ldkv,
               __nv_bfloat16* __restrict__ Ohi, __nv_bfloat16* __restrict__ Olo)
{
    extern __shared__ __align__(1024) char smem[];
    const uint32_t sb = (uint32_t)__cvta_generic_to_shared(smem);
    const int t = threadIdx.x;
    const int lane = t & 31, wid = t >> 5;
    const int warp_m = wid * 16;
    const int bh = blockIdx.y;
    const int b = bh / 12, h = bh % 12;
    const int q0 = blockIdx.x * 128;
    const size_t rowbase = (size_t)b * 1024;

    const __half* Qph = Qh + (rowbase + q0) * ldq + h * 64;
    const __half* Qpl = Ql + (rowbase + q0) * ldq + h * 64;
    const __half* Kph = Kh + rowbase * ldkv + h * 64;
    const __half* Kpl = Kl + rowbase * ldkv + h * 64;
    const __half* Vph = Vh + rowbase * ldkv + h * 64;
    const __half* Vpl = Vl + rowbase * ldkv + h * 64;

    auto load_kv = [&](int c, int st) {
        const int k0 = c * 64;
        const uint32_t base = sb + ATT_KV + st * ATT_KV_STAGE;
#pragma unroll
        for (int i = 0; i < 8; i++) {           // 2048 granules, 8/thread
            const int idx = t + i * 256;
            const int sel = i >> 1;             // 0:KH 1:KL 2:VH 3:VL
            const int r = (idx >> 3) & 63, g = idx & 7;
            const __half* src = (sel == 0 ? Kph : sel == 1 ? Kpl
                                 : sel == 2 ? Vph : Vpl) + (size_t)(k0 + r) * ldkv + g * 8;
            const uint32_t off = base + sel * 8192 +
                                 (uint32_t)(r * 128 + ((g ^ (r & 7)) << 4));
            cp16(off, src);
        }
    };

    // prologue: Q (hi+lo) + chunk 0
#pragma unroll
    for (int i = 0; i < 8; i++) {               // Q: 2048 granules, 8/thread
        const int idx = t + i * 256;
        const int sel = i >> 2;                 // 0:QH 1:QL
        const int r = (idx >> 3) & 127, g = idx & 7;
        const __half* src = (sel ? Qpl : Qph) + (size_t)r * ldq + g * 8;
        const uint32_t off = sb + (sel ? ATT_QL : ATT_QH) +
                             (uint32_t)(r * 128 + ((g ^ (r & 7)) << 4));
        cp16(off, src);
    }
    load_kv(0, 0);
    asm volatile("cp.async.commit_group;");

    float m_i[2], l_i[2], accO[8][4];
    m_i[0] = m_i[1] = -1e30f;
    l_i[0] = l_i[1] = 0.f;
#pragma unroll
    for (int f = 0; f < 8; f++)
#pragma unroll
        for (int v = 0; v < 4; v++) accO[f][v] = 0.f;

    const int f16  = lane & 15;
    const int gsel = lane >> 4;
    const int qrow = warp_m + f16;
    const uint32_t q_off = (uint32_t)(qrow * 128);
    const int qswz = qrow & 7;
    const int kswz = f16 & 7;
    const int vrow_l = (lane & 7) + 8 * ((lane >> 3) & 1);
    const int vswz = vrow_l & 7;

    for (int c = 0; c < 16; ++c) {
        const int st = c & 1;
        asm volatile("cp.async.wait_group 0;");
        __syncthreads();
        const uint32_t kvb = sb + ATT_KV + st * ATT_KV_STAGE;

        // ---- S = Q K^T ----
        float sf[8][4];
#pragma unroll
        for (int f = 0; f < 8; f++)
#pragma unroll
            for (int v = 0; v < 4; v++) sf[f][v] = 0.f;

#pragma unroll
        for (int ks = 0; ks < 4; ks++) {
            const int kg = 2 * ks + gsel;
            uint32_t qh[4], ql[4];
            const uint32_t qa = sb + q_off + (uint32_t)((kg ^ qswz) << 4);
            ldsm4(qh, ATT_QH + qa);
            ldsm4(ql, ATT_QL + qa);

            uint32_t kh[4][4], kl[4][4];
#pragma unroll
            for (int np = 0; np < 4; np++) {
                const uint32_t ka = kvb + (uint32_t)((np * 16 + f16) * 128) +
                                    (uint32_t)((kg ^ kswz) << 4);
                ldsm4(kh[np], ATT_KHo + ka);
                ldsm4(kl[np], ATT_KLo + ka);
            }
#pragma unroll
            for (int np = 0; np < 4; np++) {
                mma_f16(sf[2 * np],     qh, kh[np][0], kh[np][2]);
                mma_f16(sf[2 * np + 1], qh, kh[np][1], kh[np][3]);
            }
#pragma unroll
            for (int np = 0; np < 4; np++) {
                mma_f16(sf[2 * np],     qh, kl[np][0], kl[np][2]);
                mma_f16(sf[2 * np + 1], qh, kl[np][1], kl[np][3]);
            }
#pragma unroll
            for (int np = 0; np < 4; np++) {
                mma_f16(sf[2 * np],     ql, kh[np][0], kh[np][2]);
                mma_f16(sf[2 * np + 1], ql, kh[np][1], kh[np][3]);
            }
        }

        // prefetch next chunk (in flight during softmax + PV)
        if (c + 1 < 16) {
            load_kv(c + 1, st ^ 1);
            asm volatile("cp.async.commit_group;");
        }

        // ---- softmax (scale 1/8 folded here) ----
#pragma unroll
        for (int f = 0; f < 8; f++) {
            sf[f][0] *= 0.125f; sf[f][1] *= 0.125f;
            sf[f][2] *= 0.125f; sf[f][3] *= 0.125f;
        }
        float mx0 = -1e30f, mx1 = -1e30f;
#pragma unroll
        for (int f = 0; f < 8; f++) {
            mx0 = fmaxf(mx0, fmaxf(sf[f][0], sf[f][1]));
            mx1 = fmaxf(mx1, fmaxf(sf[f][2], sf[f][3]));
        }
        mx0 = fmaxf(mx0, __shfl_xor_sync(0xffffffffu, mx0, 1));
        mx0 = fmaxf(mx0, __shfl_xor_sync(0xffffffffu, mx0, 2));
        mx1 = fmaxf(mx1, __shfl_xor_sync(0xffffffffu, mx1, 1));
        mx1 = fmaxf(mx1, __shfl_xor_sync(0xffffffffu, mx1, 2));

        const float mn0 = fmaxf(m_i[0], mx0);
        const float mn1 = fmaxf(m_i[1], mx1);
        const float al0 = __expf(m_i[0] - mn0);
        const float al1 = __expf(m_i[1] - mn1);
        m_i[0] = mn0; m_i[1] = mn1;

        uint32_t ph0[8], ph1[8], pl0[8], pl1[8];
        float sum0 = 0.f, sum1 = 0.f;
#pragma unroll
        for (int f = 0; f < 8; f++) {
            float p0 = __expf(sf[f][0] - mn0);
            float p1 = __expf(sf[f][1] - mn0);
            float p2 = __expf(sf[f][2] - mn1);
            float p3 = __expf(sf[f][3] - mn1);
            sum0 += p0 + p1;
            sum1 += p2 + p3;
            __half2 a = __floats2half2_rn(p0, p1);
            float2 af = __half22float2(a);
            ph0[f] = h2u(a);
            pl0[f] = h2u(__floats2half2_rn(p0 - af.x, p1 - af.y));
            __half2 cc = __floats2half2_rn(p2, p3);
            float2 cf = __half22float2(cc);
            ph1[f] = h2u(cc);
            pl1[f] = h2u(__floats2half2_rn(p2 - cf.x, p3 - cf.y));
        }
        sum0 += __shfl_xor_sync(0xffffffffu, sum0, 1);
        sum0 += __shfl_xor_sync(0xffffffffu, sum0, 2);
        sum1 += __shfl_xor_sync(0xffffffffu, sum1, 1);
        sum1 += __shfl_xor_sync(0xffffffffu, sum1, 2);
        l_i[0] = l_i[0] * al0 + sum0;
        l_i[1] = l_i[1] * al1 + sum1;

#pragma unroll
        for (int f = 0; f < 8; f++) {
            accO[f][0] *= al0; accO[f][1] *= al0;
            accO[f][2] *= al1; accO[f][3] *= al1;
        }

        // ---- O += P V ----
#pragma unroll
        for (int ks = 0; ks < 4; ks++) {
            uint32_t ah[4]  = {ph0[2 * ks], ph1[2 * ks], ph0[2 * ks + 1], ph1[2 * ks + 1]};
            uint32_t alr[4] = {pl0[2 * ks], pl1[2 * ks], pl0[2 * ks + 1], pl1[2 * ks + 1]};
            const int vrow = ks * 16 + vrow_l;
            uint32_t vh[4][4], vl[4][4];
#pragma unroll
            for (int g2 = 0; g2 < 4; g2++) {
                const int vg = 2 * g2 + gsel;
                const uint32_t va = kvb + (uint32_t)(vrow * 128) +
                                    (uint32_t)((vg ^ vswz) << 4);
                ldsm4t(vh[g2], ATT_VHo + va);
                ldsm4t(vl[g2], ATT_VLo + va);
            }
#pragma unroll
            for (int g2 = 0; g2 < 4; g2++) {
                mma_f16(accO[2 * g2],     ah, vh[g2][0], vh[g2][1]);
                mma_f16(accO[2 * g2 + 1], ah, vh[g2][2], vh[g2][3]);
            }
#pragma unroll
            for (int g2 = 0; g2 < 4; g2++) {
                mma_f16(accO[2 * g2],     ah, vl[g2][0], vl[g2][1]);
                mma_f16(accO[2 * g2 + 1], ah, vl[g2][2], vl[g2][3]);
            }
#pragma unroll
            for (int g2 = 0; g2 < 4; g2++) {
                mma_f16(accO[2 * g2],     alr, vh[g2][0], vh[g2][1]);
                mma_f16(accO[2 * g2 + 1], alr, vh[g2][2], vh[g2][3]);
            }
        }
    }

    // ---- epilogue: normalize + bf16 hi/lo split (feeds proj GEMM) ----
    const float inv0 = 1.f / l_i[0];
    const float inv1 = 1.f / l_i[1];
    const size_t r0 = rowbase + q0 + warp_m + (lane >> 2);
    const size_t r1 = r0 + 8;
    const int colb = h * 64 + (lane & 3) * 2;
#pragma unroll
    for (int f = 0; f < 8; f++) {
        float v00 = accO[f][0] * inv0, v01 = accO[f][1] * inv0;
        float v10 = accO[f][2] * inv1, v11 = accO[f][3] * inv1;
        __nv_bfloat16 h00 = __float2bfloat16_rn(v00);
        __nv_bfloat16 h01 = __float2bfloat16_rn(v01);
        __nv_bfloat16 h10 = __float2bfloat16_rn(v10);
        __nv_bfloat16 h11 = __float2bfloat16_rn(v11);
        __nv_bfloat16 l00 = __float2bfloat16_rn(v00 - __bfloat162float(h00));
        __nv_bfloat16 l01 = __float2bfloat16_rn(v01 - __bfloat162float(h01));
        __nv_bfloat16 l10 = __float2bfloat16_rn(v10 - __bfloat162float(h10));
        __nv_bfloat16 l11 = __float2bfloat16_rn(v11 - __bfloat162float(h11));
        const size_t o0 = r0 * 768 + colb + 8 * f;
        const size_t o1 = r1 * 768 + colb + 8 * f;
        *(ushort2*)(Ohi + o0) = make_ushort2(__bfloat16_as_ushort(h00), __bfloat16_as_ushort(h01));
        *(ushort2*)(Olo + o0) = make_ushort2(__bfloat16_as_ushort(l00), __bfloat16_as_ushort(l01));
        *(ushort2*)(Ohi + o1) = make_ushort2(__bfloat16_as_ushort(h10), __bfloat16_as_ushort(h11));
        *(ushort2*)(Olo + o1) = make_ushort2(__bfloat16_as_ushort(l10), __bfloat16_as_ushort(l11));
    }
}

// ================= launch =================
extern "C" void kernel_launch(void* const* d_in, const int* in_sizes, int n_in,
                              void* d_out, int out_size)
{
    const float* x      = (const float*)d_in[0];
    const float* x2     = (const float*)d_in[1];
    const float* qkv_w  = (const float*)d_in[2];
    const float* proj_w = (const float*)d_in[3];
    const float* proj_b = (const float*)d_in[4];
    float* out = (float*)d_out;

    __half *qkvh, *qkvl, *kv2h, *kv2l;
    __nv_bfloat16 *xhi, *xlo, *x2hi, *x2lo, *wqhi, *wqlo, *wphi, *wplo;
    __nv_bfloat16 *o1hi, *o1lo, *o2hi, *o2lo;
    cudaGetSymbolAddress((void**)&qkvh, g_qkvh);
    cudaGetSymbolAddress((void**)&qkvl, g_qkvl);
    cudaGetSymbolAddress((void**)&kv2h, g_kv2h);
    cudaGetSymbolAddress((void**)&kv2l, g_kv2l);
    cudaGetSymbolAddress((void**)&xhi,  g_xhi);
    cudaGetSymbolAddress((void**)&xlo,  g_xlo);
    cudaGetSymbolAddress((void**)&x2hi, g_x2hi);
    cudaGetSymbolAddress((void**)&x2lo, g_x2lo);
    cudaGetSymbolAddress((void**)&wqhi, g_wqhi);
    cudaGetSymbolAddress((void**)&wqlo, g_wqlo);
    cudaGetSymbolAddress((void**)&wphi, g_wphi);
    cudaGetSymbolAddress((void**)&wplo, g_wplo);
    cudaGetSymbolAddress((void**)&o1hi, g_o1hi);
    cudaGetSymbolAddress((void**)&o1lo, g_o1lo);
    cudaGetSymbolAddress((void**)&o2hi, g_o2hi);
    cudaGetSymbolAddress((void**)&o2lo, g_o2lo);

    cudaFuncSetAttribute(gemm_hmma, cudaFuncAttributeMaxDynamicSharedMemorySize, GEMM_SMEM);
    cudaFuncSetAttribute(attn_hmma, cudaFuncAttributeMaxDynamicSharedMemorySize, ATT_SMEM);

    const int M = 8192;

    {
        int n4 = 8192 * 768 / 4;
        split_bf16<<<n4 / 256, 256>>>((const float4*)x,  (uint2*)xhi,  (uint2*)xlo,  n4);
        split_bf16<<<n4 / 256, 256>>>((const float4*)x2, (uint2*)x2hi, (uint2*)x2lo, n4);
    }
    {
        int n4 = 2304 * 768 / 4;
        split_bf16<<<n4 / 256, 256>>>((const float4*)qkv_w, (uint2*)wqhi, (uint2*)wqlo, n4);
    }
    {
        int n4 = 768 * 768 / 4;
        split_bf16<<<n4 / 256, 256>>>((const float4*)proj_w, (uint2*)wphi, (uint2*)wplo, n4);
    }

    // QKV (fp16 hi/lo out) and KV2
    gemm_hmma<<<dim3(2304 / 64, M / 128), 256, GEMM_SMEM>>>(
        xhi, xlo, wqhi, wqlo, nullptr, nullptr, qkvh, qkvl, 2304, 0, 1);
    gemm_hmma<<<dim3(1536 / 64, M / 128), 256, GEMM_SMEM>>>(
        x2hi, x2lo, wqhi, wqlo, nullptr, nullptr, kv2h, kv2l, 1536, 768, 1);

    // attention (cp.async pipelined, conversion-free)
    attn_hmma<<<dim3(8, 96), 256, ATT_SMEM>>>(
        qkvh, qkvl, 2304, qkvh + 768, qkvl + 768, qkvh + 1536, qkvl + 1536, 2304,
        o1hi, o1lo);
    attn_hmma<<<dim3(8, 96), 256, ATT_SMEM>>>(
        qkvh, qkvl, 2304, kv2h, kv2l, kv2h + 768, kv2l + 768, 1536,
        o2hi, o2lo);

    // output projections (+bias) into d_out
    gemm_hmma<<<dim3(768 / 64, M / 128), 256, GEMM_SMEM>>>(
        o1hi, o1lo, wphi, wplo, out, proj_b, nullptr, nullptr, 768, 0, 0);
    gemm_hmma<<<dim3(768 / 64, M / 128), 256, GEMM_SMEM>>>(
        o2hi, o2lo, wphi, wplo, out + (size_t)M * 768, proj_b, nullptr, nullptr, 768, 0, 0);
}

// round 10
// speedup vs baseline: 3.6653x; 1.0584x over previous
#include <cuda_runtime.h>
#include <cuda_bf16.h>
#include <cuda_fp16.h>
#include <cstdint>

// ================= scratch (no allocations allowed) =================
__device__ __align__(256) __half g_qkvh[8192 * 2304], g_qkvl[8192 * 2304]; // q|k|v fp16 hi/lo
__device__ __align__(256) __half g_kv2h[8192 * 1536], g_kv2l[8192 * 1536]; // k2|v2 fp16 hi/lo

__device__ __align__(256) __nv_bfloat16 g_xhi[8192 * 768],  g_xlo[8192 * 768];
__device__ __align__(256) __nv_bfloat16 g_x2hi[8192 * 768], g_x2lo[8192 * 768];
__device__ __align__(256) __nv_bfloat16 g_wqhi[2304 * 768], g_wqlo[2304 * 768];
__device__ __align__(256) __nv_bfloat16 g_wphi[768 * 768],  g_wplo[768 * 768];
__device__ __align__(256) __nv_bfloat16 g_o1hi[8192 * 768], g_o1lo[8192 * 768];
__device__ __align__(256) __nv_bfloat16 g_o2hi[8192 * 768], g_o2lo[8192 * 768];

// ================= helpers =================
__device__ __forceinline__ void cp16(uint32_t s, const void* g) {
    asm volatile("cp.async.cg.shared.global [%0], [%1], 16;" :: "r"(s), "l"(g));
}

__device__ __forceinline__ void ldsm4(uint32_t* r, uint32_t addr) {
    asm volatile("ldmatrix.sync.aligned.m8n8.x4.shared.b16 {%0,%1,%2,%3}, [%4];"
                 : "=r"(r[0]), "=r"(r[1]), "=r"(r[2]), "=r"(r[3]) : "r"(addr));
}

__device__ __forceinline__ void ldsm4t(uint32_t* r, uint32_t addr) {
    asm volatile("ldmatrix.sync.aligned.m8n8.x4.trans.shared.b16 {%0,%1,%2,%3}, [%4];"
                 : "=r"(r[0]), "=r"(r[1]), "=r"(r[2]), "=r"(r[3]) : "r"(addr));
}

__device__ __forceinline__ void mma16816(float* c, const uint32_t* a,
                                         uint32_t b0, uint32_t b1) {
    asm volatile(
        "mma.sync.aligned.m16n8k16.row.col.f32.bf16.bf16.f32 "
        "{%0,%1,%2,%3}, {%4,%5,%6,%7}, {%8,%9}, {%0,%1,%2,%3};"
        : "+f"(c[0]), "+f"(c[1]), "+f"(c[2]), "+f"(c[3])
        : "r"(a[0]), "r"(a[1]), "r"(a[2]), "r"(a[3]), "r"(b0), "r"(b1));
}

__device__ __forceinline__ void mma_f16(float* c, const uint32_t* a,
                                        uint32_t b0, uint32_t b1) {
    asm volatile(
        "mma.sync.aligned.m16n8k16.row.col.f32.f16.f16.f32 "
        "{%0,%1,%2,%3}, {%4,%5,%6,%7}, {%8,%9}, {%0,%1,%2,%3};"
        : "+f"(c[0]), "+f"(c[1]), "+f"(c[2]), "+f"(c[3])
        : "r"(a[0]), "r"(a[1]), "r"(a[2]), "r"(a[3]), "r"(b0), "r"(b1));
}

__device__ __forceinline__ uint32_t h2u(__half2 h) { return *(uint32_t*)&h; }

// ================= bf16 hi/lo split =================
__global__ __launch_bounds__(256)
void split_bf16(const float4* __restrict__ src, uint2* __restrict__ hi,
                uint2* __restrict__ lo, int n4)
{
    int i = blockIdx.x * blockDim.x + threadIdx.x;
    if (i >= n4) return;
    float4 v = src[i];
    float f[4] = {v.x, v.y, v.z, v.w};
    uint32_t h[4], l[4];
#pragma unroll
    for (int j = 0; j < 4; j++) {
        __nv_bfloat16 hb = __float2bfloat16_rn(f[j]);
        float r = f[j] - __bfloat162float(hb);
        __nv_bfloat16 lb = __float2bfloat16_rn(r);
        h[j] = (uint32_t)__bfloat16_as_ushort(hb);
        l[j] = (uint32_t)__bfloat16_as_ushort(lb);
    }
    hi[i] = make_uint2(h[0] | (h[1] << 16), h[2] | (h[3] << 16));
    lo[i] = make_uint2(l[0] | (l[1] << 16), l[2] | (l[3] << 16));
}

// ================= HMMA bf16x3 GEMM: 128x64 tile, 2 CTAs/SM (at mma floor) ====
#define GT_AH 0
#define GT_AL 16384
#define GT_BH 32768
#define GT_BL 40960
#define G_STAGE 49152
#define GEMM_SMEM (2 * G_STAGE)

__global__ __launch_bounds__(256, 2)
void gemm_hmma(const __nv_bfloat16* __restrict__ Ahi, const __nv_bfloat16* __restrict__ Alo,
               const __nv_bfloat16* __restrict__ Bhi, const __nv_bfloat16* __restrict__ Blo,
               float* __restrict__ C, const float* __restrict__ bias,
               __half* __restrict__ Hh, __half* __restrict__ Hl,
               int N, int woff, int mode)
{
    extern __shared__ __align__(1024) char smem[];
    const uint32_t sb = (uint32_t)__cvta_generic_to_shared(smem);
    const int t = threadIdx.x;
    const int wid = t >> 5, lane = t & 31;
    const int m0 = blockIdx.y * 128;
    const int n0 = blockIdx.x * 64;
    const int warp_m = (wid >> 1) * 32;
    const int warp_n = (wid & 1) * 32;
    const int K = 768, NC = 12;

    float acc[2][4][4];
#pragma unroll
    for (int i = 0; i < 2; i++)
#pragma unroll
        for (int j = 0; j < 4; j++)
#pragma unroll
            for (int v = 0; v < 4; v++) acc[i][j][v] = 0.f;

    const __nv_bfloat16* Ah = Ahi + (size_t)m0 * K;
    const __nv_bfloat16* Al = Alo + (size_t)m0 * K;
    const __nv_bfloat16* Bh = Bhi + (size_t)(woff + n0) * K;
    const __nv_bfloat16* Bl = Blo + (size_t)(woff + n0) * K;

    auto load_chunk = [&](int c, int st) {
        const int kc = c * 64;
        const uint32_t base = sb + st * G_STAGE;
#pragma unroll
        for (int i = 0; i < 4; i++) {
            const int gi = t + i * 256;
            const int row = gi >> 3, g = gi & 7;
            const uint32_t loff = (uint32_t)(row * 128 + ((g ^ (row & 7)) << 4));
            const size_t goff = (size_t)row * K + kc + g * 8;
            cp16(base + GT_AH + loff, Ah + goff);
            cp16(base + GT_AL + loff, Al + goff);
        }
#pragma unroll
        for (int i = 0; i < 2; i++) {
            const int gi = t + i * 256;
            const int row = gi >> 3, g = gi & 7;
            const uint32_t loff = (uint32_t)(row * 128 + ((g ^ (row & 7)) << 4));
            const size_t goff = (size_t)row * K + kc + g * 8;
            cp16(base + GT_BH + loff, Bh + goff);
            cp16(base + GT_BL + loff, Bl + goff);
        }
        asm volatile("cp.async.commit_group;");
    };

    const int fr   = lane & 15;
    const int half = lane >> 4;
    const int arow = warp_m + fr;
    const int brow = warp_n + fr;
    const int aswz = arow & 7;
    const int bswz = brow & 7;
    const uint32_t arow_off = (uint32_t)(arow * 128);
    const uint32_t brow_off = (uint32_t)(brow * 128);

    load_chunk(0, 0);

    for (int c = 0; c < NC; ++c) {
        const int st = c & 1;
        if (c + 1 < NC) {
            load_chunk(c + 1, st ^ 1);
            asm volatile("cp.async.wait_group 1;");
        } else {
            asm volatile("cp.async.wait_group 0;");
        }
        __syncthreads();

        const uint32_t base = sb + st * G_STAGE;
#pragma unroll
        for (int kk = 0; kk < 4; kk++) {
            const int kg = kk * 2 + half;
            const uint32_t aoff = arow_off + (uint32_t)((kg ^ aswz) << 4);
            const uint32_t boff = brow_off + (uint32_t)((kg ^ bswz) << 4);

            uint32_t ah[2][4], al[2][4], bh[2][4], bl[2][4];
#pragma unroll
            for (int mi = 0; mi < 2; mi++) {
                ldsm4(ah[mi], base + GT_AH + aoff + mi * (16 * 128));
                ldsm4(al[mi], base + GT_AL + aoff + mi * (16 * 128));
            }
#pragma unroll
            for (int bj = 0; bj < 2; bj++) {
                ldsm4(bh[bj], base + GT_BH + boff + bj * (16 * 128));
                ldsm4(bl[bj], base + GT_BL + boff + bj * (16 * 128));
            }
#pragma unroll
            for (int mi = 0; mi < 2; mi++)
#pragma unroll
                for (int bj = 0; bj < 2; bj++) {
                    mma16816(acc[mi][bj * 2],     ah[mi], bh[bj][0], bh[bj][2]);
                    mma16816(acc[mi][bj * 2 + 1], ah[mi], bh[bj][1], bh[bj][3]);
                }
#pragma unroll
            for (int mi = 0; mi < 2; mi++)
#pragma unroll
                for (int bj = 0; bj < 2; bj++) {
                    mma16816(acc[mi][bj * 2],     ah[mi], bl[bj][0], bl[bj][2]);
                    mma16816(acc[mi][bj * 2 + 1], ah[mi], bl[bj][1], bl[bj][3]);
                }
#pragma unroll
            for (int mi = 0; mi < 2; mi++)
#pragma unroll
                for (int bj = 0; bj < 2; bj++) {
                    mma16816(acc[mi][bj * 2],     al[mi], bh[bj][0], bh[bj][2]);
                    mma16816(acc[mi][bj * 2 + 1], al[mi], bh[bj][1], bh[bj][3]);
                }
        }
        __syncthreads();
    }

#pragma unroll
    for (int mi = 0; mi < 2; mi++) {
        const int r = m0 + warp_m + mi * 16 + (lane >> 2);
#pragma unroll
        for (int j = 0; j < 4; j++) {
            const int col = n0 + warp_n + j * 8 + (lane & 3) * 2;
            float v00 = acc[mi][j][0], v01 = acc[mi][j][1];
            float v10 = acc[mi][j][2], v11 = acc[mi][j][3];
            if (mode == 0) {
                const float b0 = bias[col], b1 = bias[col + 1];
                *(float2*)(C + (size_t)r * N + col)       = make_float2(v00 + b0, v01 + b1);
                *(float2*)(C + (size_t)(r + 8) * N + col) = make_float2(v10 + b0, v11 + b1);
            } else {
                __half h00 = __float2half_rn(v00), h01 = __float2half_rn(v01);
                __half h10 = __float2half_rn(v10), h11 = __float2half_rn(v11);
                __half l00 = __float2half_rn(v00 - __half2float(h00));
                __half l01 = __float2half_rn(v01 - __half2float(h01));
                __half l10 = __float2half_rn(v10 - __half2float(h10));
                __half l11 = __float2half_rn(v11 - __half2float(h11));
                const size_t o0 = (size_t)r * N + col;
                const size_t o1 = (size_t)(r + 8) * N + col;
                *(ushort2*)(Hh + o0) = make_ushort2(__half_as_ushort(h00), __half_as_ushort(h01));
                *(ushort2*)(Hl + o0) = make_ushort2(__half_as_ushort(l00), __half_as_ushort(l01));
                *(ushort2*)(Hh + o1) = make_ushort2(__half_as_ushort(h10), __half_as_ushort(h11));
                *(ushort2*)(Hl + o1) = make_ushort2(__half_as_ushort(l10), __half_as_ushort(l11));
            }
        }
    }
}

// ================= HMMA flash attention: 2 CTAs/SM, merged branches ===========
// grid (8 q-tiles, 96 b*h, 2 branches). smem 96KB: Q hi/lo + 2 KV stages.
#define ATT_QH 0
#define ATT_QL 16384
#define ATT_KV 32768
#define ATT_KV_STAGE 32768
#define ATT_SMEM 98304
#define ATT_KHo 0
#define ATT_KLo 8192
#define ATT_VHo 16384
#define ATT_VLo 24576

__global__ __launch_bounds__(256, 2)
void attn_hmma(const __half* __restrict__ Qh, const __half* __restrict__ Ql, int ldq,
               const __half* __restrict__ K1h, const __half* __restrict__ K1l,
               const __half* __restrict__ V1h, const __half* __restrict__ V1l, int ld1,
               const __half* __restrict__ K2h, const __half* __restrict__ K2l,
               const __half* __restrict__ V2h, const __half* __restrict__ V2l, int ld2,
               __nv_bfloat16* __restrict__ O1hi, __nv_bfloat16* __restrict__ O1lo,
               __nv_bfloat16* __restrict__ O2hi, __nv_bfloat16* __restrict__ O2lo)
{
    extern __shared__ __align__(1024) char smem[];
    const uint32_t sb = (uint32_t)__cvta_generic_to_shared(smem);
    const int t = threadIdx.x;
    const int lane = t & 31, wid = t >> 5;
    const int warp_m = wid * 16;
    const int bh = blockIdx.y;
    const int br = blockIdx.z;
    const int b = bh / 12, h = bh % 12;
    const int q0 = blockIdx.x * 128;
    const size_t rowbase = (size_t)b * 1024;

    const int ldkv = br ? ld2 : ld1;
    const __half* Kph = (br ? K2h : K1h) + rowbase * ldkv + h * 64;
    const __half* Kpl = (br ? K2l : K1l) + rowbase * ldkv + h * 64;
    const __half* Vph = (br ? V2h : V1h) + rowbase * ldkv + h * 64;
    const __half* Vpl = (br ? V2l : V1l) + rowbase * ldkv + h * 64;
    __nv_bfloat16* Ohi = br ? O2hi : O1hi;
    __nv_bfloat16* Olo = br ? O2lo : O1lo;
    const __half* Qph = Qh + (rowbase + q0) * ldq + h * 64;
    const __half* Qpl = Ql + (rowbase + q0) * ldq + h * 64;

    auto load_kv = [&](int c, int st) {
        const int k0 = c * 64;
        const uint32_t base = sb + ATT_KV + st * ATT_KV_STAGE;
#pragma unroll
        for (int i = 0; i < 8; i++) {
            const int idx = t + i * 256;
            const int sel = i >> 1;             // 0:KH 1:KL 2:VH 3:VL
            const int r = (idx >> 3) & 63, g = idx & 7;
            const __half* src = (sel == 0 ? Kph : sel == 1 ? Kpl
                                 : sel == 2 ? Vph : Vpl) + (size_t)(k0 + r) * ldkv + g * 8;
            const uint32_t off = base + sel * 8192 +
                                 (uint32_t)(r * 128 + ((g ^ (r & 7)) << 4));
            cp16(off, src);
        }
    };

    // prologue: Q (hi+lo) + chunk 0
#pragma unroll
    for (int i = 0; i < 8; i++) {
        const int idx = t + i * 256;
        const int sel = i >> 2;                 // 0:QH 1:QL
        const int r = (idx >> 3) & 127, g = idx & 7;
        const __half* src = (sel ? Qpl : Qph) + (size_t)r * ldq + g * 8;
        const uint32_t off = sb + (sel ? ATT_QL : ATT_QH) +
                             (uint32_t)(r * 128 + ((g ^ (r & 7)) << 4));
        cp16(off, src);
    }
    load_kv(0, 0);
    asm volatile("cp.async.commit_group;");

    float m_i[2], l_i[2], accO[8][4];
    m_i[0] = m_i[1] = -1e30f;
    l_i[0] = l_i[1] = 0.f;
#pragma unroll
    for (int f = 0; f < 8; f++)
#pragma unroll
        for (int v = 0; v < 4; v++) accO[f][v] = 0.f;

    const int f16  = lane & 15;
    const int gsel = lane >> 4;
    const int qrow = warp_m + f16;
    const uint32_t q_off = (uint32_t)(qrow * 128);
    const int qswz = qrow & 7;
    const int kswz = f16 & 7;
    const int vrow_l = (lane & 7) + 8 * ((lane >> 3) & 1);
    const int vswz = vrow_l & 7;

    for (int c = 0; c < 16; ++c) {
        const int st = c & 1;
        asm volatile("cp.async.wait_group 0;");
        __syncthreads();
        const uint32_t kvb = sb + ATT_KV + st * ATT_KV_STAGE;

        // ---- S = Q K^T ----
        float sf[8][4];
#pragma unroll
        for (int f = 0; f < 8; f++)
#pragma unroll
            for (int v = 0; v < 4; v++) sf[f][v] = 0.f;

#pragma unroll
        for (int ks = 0; ks < 4; ks++) {
            const int kg = 2 * ks + gsel;
            uint32_t qh[4], ql[4];
            const uint32_t qa = sb + q_off + (uint32_t)((kg ^ qswz) << 4);
            ldsm4(qh, ATT_QH + qa);
            ldsm4(ql, ATT_QL + qa);

            uint32_t kh[4][4], kl[4][4];
#pragma unroll
            for (int np = 0; np < 4; np++) {
                const uint32_t ka = kvb + (uint32_t)((np * 16 + f16) * 128) +
                                    (uint32_t)((kg ^ kswz) << 4);
                ldsm4(kh[np], ATT_KHo + ka);
                ldsm4(kl[np], ATT_KLo + ka);
            }
#pragma unroll
            for (int np = 0; np < 4; np++) {
                mma_f16(sf[2 * np],     qh, kh[np][0], kh[np][2]);
                mma_f16(sf[2 * np + 1], qh, kh[np][1], kh[np][3]);
            }
#pragma unroll
            for (int np = 0; np < 4; np++) {
                mma_f16(sf[2 * np],     qh, kl[np][0], kl[np][2]);
                mma_f16(sf[2 * np + 1], qh, kl[np][1], kl[np][3]);
            }
#pragma unroll
            for (int np = 0; np < 4; np++) {
                mma_f16(sf[2 * np],     ql, kh[np][0], kh[np][2]);
                mma_f16(sf[2 * np + 1], ql, kh[np][1], kh[np][3]);
            }
        }

        // prefetch next chunk (in flight during softmax + PV)
        if (c + 1 < 16) {
            load_kv(c + 1, st ^ 1);
            asm volatile("cp.async.commit_group;");
        }

        // ---- softmax (scale 1/8 folded; P kept as fp32 in sf) ----
        float mx0 = -1e30f, mx1 = -1e30f;
#pragma unroll
        for (int f = 0; f < 8; f++) {
            sf[f][0] *= 0.125f; sf[f][1] *= 0.125f;
            sf[f][2] *= 0.125f; sf[f][3] *= 0.125f;
            mx0 = fmaxf(mx0, fmaxf(sf[f][0], sf[f][1]));
            mx1 = fmaxf(mx1, fmaxf(sf[f][2], sf[f][3]));
        }
        mx0 = fmaxf(mx0, __shfl_xor_sync(0xffffffffu, mx0, 1));
        mx0 = fmaxf(mx0, __shfl_xor_sync(0xffffffffu, mx0, 2));
        mx1 = fmaxf(mx1, __shfl_xor_sync(0xffffffffu, mx1, 1));
        mx1 = fmaxf(mx1, __shfl_xor_sync(0xffffffffu, mx1, 2));

        const float mn0 = fmaxf(m_i[0], mx0);
        const float mn1 = fmaxf(m_i[1], mx1);
        const float al0 = __expf(m_i[0] - mn0);
        const float al1 = __expf(m_i[1] - mn1);
        m_i[0] = mn0; m_i[1] = mn1;

        float sum0 = 0.f, sum1 = 0.f;
#pragma unroll
        for (int f = 0; f < 8; f++) {
            sf[f][0] = __expf(sf[f][0] - mn0);
            sf[f][1] = __expf(sf[f][1] - mn0);
            sf[f][2] = __expf(sf[f][2] - mn1);
            sf[f][3] = __expf(sf[f][3] - mn1);
            sum0 += sf[f][0] + sf[f][1];
            sum1 += sf[f][2] + sf[f][3];
        }
        sum0 += __shfl_xor_sync(0xffffffffu, sum0, 1);
        sum0 += __shfl_xor_sync(0xffffffffu, sum0, 2);
        sum1 += __shfl_xor_sync(0xffffffffu, sum1, 1);
        sum1 += __shfl_xor_sync(0xffffffffu, sum1, 2);
        l_i[0] = l_i[0] * al0 + sum0;
        l_i[1] = l_i[1] * al1 + sum1;

#pragma unroll
        for (int f = 0; f < 8; f++) {
            accO[f][0] *= al0; accO[f][1] *= al0;
            accO[f][2] *= al1; accO[f][3] *= al1;
        }

        // ---- O += P V (P packed per-ks to shrink register live ranges) ----
#pragma unroll
        for (int ks = 0; ks < 4; ks++) {
            const int f0 = 2 * ks, f1 = 2 * ks + 1;
            uint32_t ah[4], alr[4];
            {
                __half2 a0 = __floats2half2_rn(sf[f0][0], sf[f0][1]);
                __half2 a1 = __floats2half2_rn(sf[f0][2], sf[f0][3]);
                __half2 a2 = __floats2half2_rn(sf[f1][0], sf[f1][1]);
                __half2 a3 = __floats2half2_rn(sf[f1][2], sf[f1][3]);
                float2 r0 = __half22float2(a0), r1 = __half22float2(a1);
                float2 r2 = __half22float2(a2), r3 = __half22float2(a3);
                ah[0] = h2u(a0); ah[1] = h2u(a1); ah[2] = h2u(a2); ah[3] = h2u(a3);
                alr[0] = h2u(__floats2half2_rn(sf[f0][0] - r0.x, sf[f0][1] - r0.y));
                alr[1] = h2u(__floats2half2_rn(sf[f0][2] - r1.x, sf[f0][3] - r1.y));
                alr[2] = h2u(__floats2half2_rn(sf[f1][0] - r2.x, sf[f1][1] - r2.y));
                alr[3] = h2u(__floats2half2_rn(sf[f1][2] - r3.x, sf[f1][3] - r3.y));
            }
            const int vrow = ks * 16 + vrow_l;
            uint32_t vh[4][4], vl[4][4];
#pragma unroll
            for (int g2 = 0; g2 < 4; g2++) {
                const int vg = 2 * g2 + gsel;
                const uint32_t va = kvb + (uint32_t)(vrow * 128) +
                                    (uint32_t)((vg ^ vswz) << 4);
                ldsm4t(vh[g2], ATT_VHo + va);
                ldsm4t(vl[g2], ATT_VLo + va);
            }
#pragma unroll
            for (int g2 = 0; g2 < 4; g2++) {
                mma_f16(accO[2 * g2],     ah, vh[g2][0], vh[g2][1]);
                mma_f16(accO[2 * g2 + 1], ah, vh[g2][2], vh[g2][3]);
            }
#pragma unroll
            for (int g2 = 0; g2 < 4; g2++) {
                mma_f16(accO[2 * g2],     ah, vl[g2][0], vl[g2][1]);
                mma_f16(accO[2 * g2 + 1], ah, vl[g2][2], vl[g2][3]);
            }
#pragma unroll
            for (int g2 = 0; g2 < 4; g2++) {
                mma_f16(accO[2 * g2],     alr, vh[g2][0], vh[g2][1]);
                mma_f16(accO[2 * g2 + 1], alr, vh[g2][2], vh[g2][3]);
            }
        }
    }

    // ---- epilogue: normalize + bf16 hi/lo split (feeds proj GEMM) ----
    const float inv0 = 1.f / l_i[0];
    const float inv1 = 1.f / l_i[1];
    const size_t r0 = rowbase + q0 + warp_m + (lane >> 2);
    const size_t r1 = r0 + 8;
    const int colb = h * 64 + (lane & 3) * 2;
#pragma unroll
    for (int f = 0; f < 8; f++) {
        float v00 = accO[f][0] * inv0, v01 = accO[f][1] * inv0;
        float v10 = accO[f][2] * inv1, v11 = accO[f][3] * inv1;
        __nv_bfloat16 h00 = __float2bfloat16_rn(v00);
        __nv_bfloat16 h01 = __float2bfloat16_rn(v01);
        __nv_bfloat16 h10 = __float2bfloat16_rn(v10);
        __nv_bfloat16 h11 = __float2bfloat16_rn(v11);
        __nv_bfloat16 l00 = __float2bfloat16_rn(v00 - __bfloat162float(h00));
        __nv_bfloat16 l01 = __float2bfloat16_rn(v01 - __bfloat162float(h01));
        __nv_bfloat16 l10 = __float2bfloat16_rn(v10 - __bfloat162float(h10));
        __nv_bfloat16 l11 = __float2bfloat16_rn(v11 - __bfloat162float(h11));
        const size_t o0 = r0 * 768 + colb + 8 * f;
        const size_t o1 = r1 * 768 + colb + 8 * f;
        *(ushort2*)(Ohi + o0) = make_ushort2(__bfloat16_as_ushort(h00), __bfloat16_as_ushort(h01));
        *(ushort2*)(Olo + o0) = make_ushort2(__bfloat16_as_ushort(l00), __bfloat16_as_ushort(l01));
        *(ushort2*)(Ohi + o1) = make_ushort2(__bfloat16_as_ushort(h10), __bfloat16_as_ushort(h11));
        *(ushort2*)(Olo + o1) = make_ushort2(__bfloat16_as_ushort(l10), __bfloat16_as_ushort(l11));
    }
}

// ================= launch =================
extern "C" void kernel_launch(void* const* d_in, const int* in_sizes, int n_in,
                              void* d_out, int out_size)
{
    const float* x      = (const float*)d_in[0];
    const float* x2     = (const float*)d_in[1];
    const float* qkv_w  = (const float*)d_in[2];
    const float* proj_w = (const float*)d_in[3];
    const float* proj_b = (const float*)d_in[4];
    float* out = (float*)d_out;

    __half *qkvh, *qkvl, *kv2h, *kv2l;
    __nv_bfloat16 *xhi, *xlo, *x2hi, *x2lo, *wqhi, *wqlo, *wphi, *wplo;
    __nv_bfloat16 *o1hi, *o1lo, *o2hi, *o2lo;
    cudaGetSymbolAddress((void**)&qkvh, g_qkvh);
    cudaGetSymbolAddress((void**)&qkvl, g_qkvl);
    cudaGetSymbolAddress((void**)&kv2h, g_kv2h);
    cudaGetSymbolAddress((void**)&kv2l, g_kv2l);
    cudaGetSymbolAddress((void**)&xhi,  g_xhi);
    cudaGetSymbolAddress((void**)&xlo,  g_xlo);
    cudaGetSymbolAddress((void**)&x2hi, g_x2hi);
    cudaGetSymbolAddress((void**)&x2lo, g_x2lo);
    cudaGetSymbolAddress((void**)&wqhi, g_wqhi);
    cudaGetSymbolAddress((void**)&wqlo, g_wqlo);
    cudaGetSymbolAddress((void**)&wphi, g_wphi);
    cudaGetSymbolAddress((void**)&wplo, g_wplo);
    cudaGetSymbolAddress((void**)&o1hi, g_o1hi);
    cudaGetSymbolAddress((void**)&o1lo, g_o1lo);
    cudaGetSymbolAddress((void**)&o2hi, g_o2hi);
    cudaGetSymbolAddress((void**)&o2lo, g_o2lo);

    cudaFuncSetAttribute(gemm_hmma, cudaFuncAttributeMaxDynamicSharedMemorySize, GEMM_SMEM);
    cudaFuncSetAttribute(attn_hmma, cudaFuncAttributeMaxDynamicSharedMemorySize, ATT_SMEM);

    const int M = 8192;

    {
        int n4 = 8192 * 768 / 4;
        split_bf16<<<n4 / 256, 256>>>((const float4*)x,  (uint2*)xhi,  (uint2*)xlo,  n4);
        split_bf16<<<n4 / 256, 256>>>((const float4*)x2, (uint2*)x2hi, (uint2*)x2lo, n4);
    }
    {
        int n4 = 2304 * 768 / 4;
        split_bf16<<<n4 / 256, 256>>>((const float4*)qkv_w, (uint2*)wqhi, (uint2*)wqlo, n4);
    }
    {
        int n4 = 768 * 768 / 4;
        split_bf16<<<n4 / 256, 256>>>((const float4*)proj_w, (uint2*)wphi, (uint2*)wplo, n4);
    }

    // QKV (fp16 hi/lo out) and KV2
    gemm_hmma<<<dim3(2304 / 64, M / 128), 256, GEMM_SMEM>>>(
        xhi, xlo, wqhi, wqlo, nullptr, nullptr, qkvh, qkvl, 2304, 0, 1);
    gemm_hmma<<<dim3(1536 / 64, M / 128), 256, GEMM_SMEM>>>(
        x2hi, x2lo, wqhi, wqlo, nullptr, nullptr, kv2h, kv2l, 1536, 768, 1);

    // both attention branches in one launch (z = branch)
    attn_hmma<<<dim3(8, 96, 2), 256, ATT_SMEM>>>(
        qkvh, qkvl, 2304,
        qkvh + 768, qkvl + 768, qkvh + 1536, qkvl + 1536, 2304,
        kv2h, kv2l, kv2h + 768, kv2l + 768, 1536,
        o1hi, o1lo, o2hi, o2lo);

    // output projections (+bias) into d_out
    gemm_hmma<<<dim3(768 / 64, M / 128), 256, GEMM_SMEM>>>(
        o1hi, o1lo, wphi, wplo, out, proj_b, nullptr, nullptr, 768, 0, 0);
    gemm_hmma<<<dim3(768 / 64, M / 128), 256, GEMM_SMEM>>>(
        o2hi, o2lo, wphi, wplo, out + (size_t)M * 768, proj_b, nullptr, nullptr, 768, 0, 0);
}